// round 14
// baseline (speedup 1.0000x reference)
#include <cuda_runtime.h>
#include <cuda_bf16.h>
#include <math.h>

#define BATCH 4
#define C 192
#define HW 16384            // 128*128
#define NPIX (BATCH*HW)     // 65536
#define NH 6
#define HD 32
#define NWIN 256
#define NTOK 256
#define LOG2E 1.44269504088896f

// ---------------- scratch (device globals; no allocations allowed) ----------
__device__ float g_y[BATCH*C*HW];
__device__ float g_a[BATCH*C*HW];
__device__ float g_b[BATCH*C*HW];
__device__ float g_qkv[(size_t)NPIX*576];
__device__ float g_tbl[961*NH];
__device__ float g_bias[NH*256*256];       // expanded CPB bias (log2-domain, pre-shifted)
__device__ float g_stats[NPIX*2];          // per-pixel LN partial (S, S2)

// ---------------- fast exp2 on the FMA pipe (input already log2-domain) -----
__device__ __forceinline__ float fexp2(float z){
    z = fmaxf(z, -126.0f);
    float mz = z + 12582912.0f;
    int   iz = __float_as_int(mz);
    float f  = z - (mz - 12582912.0f);
    float p  = 1.0f + f*(0.6931471806f + f*(0.2402265070f + f*(0.0555041087f
              + f*(0.0096181291f + f*0.0013333558f))));
    return __int_as_float(__float_as_int(p) + (iz << 23));
}

// ---------------- bf16 split helpers ---------------------------------------
__device__ __forceinline__ unsigned packbf(float lo, float hi){
    unsigned r;
    asm("cvt.rn.bf16x2.f32 %0, %1, %2;" : "=r"(r) : "f"(hi), "f"(lo));
    return r;
}
__device__ __forceinline__ float bflo(unsigned u){ return __uint_as_float(u << 16); }
__device__ __forceinline__ float bfhi(unsigned u){ return __uint_as_float(u & 0xffff0000u); }

__device__ __forceinline__ void split2(float a, float b, unsigned& h, unsigned& l){
    h = packbf(a, b);
    l = packbf(a - bflo(h), b - bfhi(h));
}

__device__ __forceinline__ void mma_bf16(float c[4], const unsigned a[4],
                                         unsigned b0, unsigned b1){
    asm("mma.sync.aligned.m16n8k16.row.col.f32.bf16.bf16.f32 "
        "{%0,%1,%2,%3},{%4,%5,%6,%7},{%8,%9},{%0,%1,%2,%3};"
        : "+f"(c[0]), "+f"(c[1]), "+f"(c[2]), "+f"(c[3])
        : "r"(a[0]), "r"(a[1]), "r"(a[2]), "r"(a[3]), "r"(b0), "r"(b1));
}

// ---------------- CPB MLP table --------------------------------------------
__global__ void k_cpb(const float* __restrict__ w1, const float* __restrict__ b1,
                      const float* __restrict__ w2, float* __restrict__ tbl)
{
    int r = blockIdx.x;
    int t = threadIdx.x;
    float dy = (float)(r / 31) - 15.0f;
    float dx = (float)(r % 31) - 15.0f;
    float u0 = dy / 15.0f * 8.0f, u1 = dx / 15.0f * 8.0f;
    float t0 = copysignf(log2f(fabsf(u0) + 1.0f) * (1.0f/3.0f), u0);
    float t1 = copysignf(log2f(fabsf(u1) + 1.0f) * (1.0f/3.0f), u1);
    float acc[6] = {0,0,0,0,0,0};
    for (int u = t; u < 512; u += 128){
        float hv = fmaxf(w1[2*u]*t0 + w1[2*u+1]*t1 + b1[u], 0.0f);
        #pragma unroll
        for (int h = 0; h < 6; h++) acc[h] += hv * w2[h*512 + u];
    }
    __shared__ float red[6][128];
    #pragma unroll
    for (int h = 0; h < 6; h++) red[h][t] = acc[h];
    __syncthreads();
    for (int off = 64; off > 0; off >>= 1){
        if (t < off){
            #pragma unroll
            for (int h = 0; h < 6; h++) red[h][t] += red[h][t+off];
        }
        __syncthreads();
    }
    if (t < 6){
        float v = red[t][0];
        tbl[r*6 + t] = 16.0f / (1.0f + expf(-v));
    }
}

// ---------------- expand CPB bias to [h][256][256], log2 domain, -m_h -------
__global__ void k_bias(const float* __restrict__ tbl, const float* __restrict__ lsc,
                       float* __restrict__ bg)
{
    int r = blockIdx.x, h = blockIdx.y, c = threadIdx.x;
    int iy = r >> 4, ix = r & 15, my = c >> 4, mx = c & 15;
    int idx = (iy - my + 15)*31 + (ix - mx + 15);
    float scale = __expf(fminf(lsc[h], 4.6051702f));
    bg[((size_t)h*256 + r)*256 + c] = (tbl[idx*6 + h] - (scale + 16.0f)) * LOG2E;
}

// ---------------- tensor-core GEMM (bf16 hi/lo split, fp32 accum) ----------
// MODE 0: p1; 1: pw; 2: p2 (gate+res->BHWC, accumulates LN stats);
// MODE 3: qkv (inline LN from raw sums); 4: proj->NCHW
// K-chunk 64 (3 chunks): A [64 rows][32 k2] stride 36 (conflict-free),
// B [32 k2][256 col] stride 264 (conflict-free). Epilogue stage (modes 2,3)
// [pixel][68] overlay.
template<int MODE>
__global__ void __launch_bounds__(256, 2)
k_gemm(const float* __restrict__ X, const float* __restrict__ W,
       const float* __restrict__ bias, const float* __restrict__ X2,
       const float* __restrict__ res, const float* __restrict__ qb,
       const float* __restrict__ vb, float* __restrict__ out,
       float* __restrict__ stats)
{
    // MODE 3 reinterprets: bias = ln_b, res = ln_g, X2 = raw stats (S, S2)
    extern __shared__ unsigned smem_u[];
    unsigned* Ah = smem_u;                  // 64*36
    unsigned* Al = Ah + 64*36;
    unsigned* Bh = Al + 64*36;              // 32*264
    unsigned* Bl = Bh + 32*264;
    float* sstat = (float*)(Bl + 32*264);   // mode 3: [256]*(mu,rs)
    float* stg = (float*)smem_u;            // overlay (modes 2,3 epilogue): [256][68]

    const int t = threadIdx.x;
    const int wid = t >> 5, lane = t & 31;
    const int gid = lane >> 2, tig = lane & 3;
    const int m0w = (wid & 1) * 32;
    const int n0w = (wid >> 1) * 64;

    const int p0  = blockIdx.x * 256;
    const int co0 = blockIdx.y * 64;
    const int bz  = (MODE <= 2) ? blockIdx.z : 0;

    const float* Xb  = (MODE <= 2) ? (X + (size_t)bz*C*HW) : X;
    const float* X2b = (MODE == 2) ? (X2 + (size_t)bz*C*HW) : nullptr;

    float c[2][8][4];
    #pragma unroll
    for (int i = 0; i < 2; i++)
        #pragma unroll
        for (int j = 0; j < 8; j++)
            #pragma unroll
            for (int q = 0; q < 4; q++) c[i][j][q] = 0.0f;

    const int ar  = t >> 2;
    const int akq = (t & 3) * 16;           // 16 k-values per thread per chunk

    if (MODE == 3){
        // per-pixel LN stats from raw sums
        float2 ssum = *(const float2*)&X2[(size_t)(p0 + t)*2];
        float mu = ssum.x * (1.0f/192.0f);
        float var = ssum.y * (1.0f/192.0f) - mu*mu;
        float rs = rsqrtf(var + 1e-5f);
        sstat[2*t] = mu; sstat[2*t+1] = rs;
    }

    for (int kc = 0; kc < 3; kc++){
        const int k0 = kc * 64;
        __syncthreads();
        // ---- A: W[co0+ar][k0+akq .. +16] -> Ah/Al [ar][akq/2 .. +8]
        {
            const float* wp = &W[(size_t)(co0 + ar)*192 + k0 + akq];
            float4 w0 = *(const float4*)wp;
            float4 w1 = *(const float4*)(wp + 4);
            float4 w2 = *(const float4*)(wp + 8);
            float4 w3 = *(const float4*)(wp + 12);
            uint4 h0, l0, h1, l1;
            split2(w0.x, w0.y, h0.x, l0.x);
            split2(w0.z, w0.w, h0.y, l0.y);
            split2(w1.x, w1.y, h0.z, l0.z);
            split2(w1.z, w1.w, h0.w, l0.w);
            split2(w2.x, w2.y, h1.x, l1.x);
            split2(w2.z, w2.w, h1.y, l1.y);
            split2(w3.x, w3.y, h1.z, l1.z);
            split2(w3.z, w3.w, h1.w, l1.w);
            *(uint4*)&Ah[ar*36 + (t&3)*8]     = h0;
            *(uint4*)&Ah[ar*36 + (t&3)*8 + 4] = h1;
            *(uint4*)&Al[ar*36 + (t&3)*8]     = l0;
            *(uint4*)&Al[ar*36 + (t&3)*8 + 4] = l1;
        }
        if (MODE <= 2){
            const int bp  = (t & 63) * 4;
            const int bk2 = t >> 6;
            #pragma unroll
            for (int r = 0; r < 8; r++){
                int k2i = bk2 + r*4;
                int k = k0 + k2i*2;
                const float* xr = Xb + (size_t)k*HW + p0 + bp;
                float4 e = *(const float4*)xr;
                float4 o = *(const float4*)(xr + HW);
                if (MODE == 2){
                    const float* mr = X2b + (size_t)k*HW + p0 + bp;
                    float4 m1 = *(const float4*)mr;
                    float4 m2 = *(const float4*)(mr + HW);
                    e.x*=m1.x; e.y*=m1.y; e.z*=m1.z; e.w*=m1.w;
                    o.x*=m2.x; o.y*=m2.y; o.z*=m2.z; o.w*=m2.w;
                }
                uint4 h, l;
                split2(e.x, o.x, h.x, l.x);
                split2(e.y, o.y, h.y, l.y);
                split2(e.z, o.z, h.z, l.z);
                split2(e.w, o.w, h.w, l.w);
                *(uint4*)&Bh[k2i*264 + bp] = h;
                *(uint4*)&Bl[k2i*264 + bp] = l;
            }
        } else {
            const int fi = t & 7;
            const int k = k0 + fi*8;
            float4 gva, gvb, bva, bvb;
            if (MODE == 3){
                gva = *(const float4*)&res[k];       // ln gamma
                gvb = *(const float4*)&res[k + 4];
                bva = *(const float4*)&bias[k];      // ln beta
                bvb = *(const float4*)&bias[k + 4];
            }
            #pragma unroll
            for (int r = 0; r < 8; r++){
                int pl = (t >> 3) + r*32;
                const float* xp = &Xb[(size_t)(p0 + pl)*192 + k];
                float4 v = *(const float4*)xp;
                float4 u = *(const float4*)(xp + 4);
                if (MODE == 3){
                    float2 st = *(const float2*)&sstat[2*pl];
                    v.x = (v.x - st.x)*st.y*gva.x + bva.x;
                    v.y = (v.y - st.x)*st.y*gva.y + bva.y;
                    v.z = (v.z - st.x)*st.y*gva.z + bva.z;
                    v.w = (v.w - st.x)*st.y*gva.w + bva.w;
                    u.x = (u.x - st.x)*st.y*gvb.x + bvb.x;
                    u.y = (u.y - st.x)*st.y*gvb.y + bvb.y;
                    u.z = (u.z - st.x)*st.y*gvb.z + bvb.z;
                    u.w = (u.w - st.x)*st.y*gvb.w + bvb.w;
                }
                unsigned h0, l0, h1, l1, h2, l2, h3, l3;
                split2(v.x, v.y, h0, l0);
                split2(v.z, v.w, h1, l1);
                split2(u.x, u.y, h2, l2);
                split2(u.z, u.w, h3, l3);
                Bh[(fi*4  )*264 + pl] = h0;
                Bh[(fi*4+1)*264 + pl] = h1;
                Bh[(fi*4+2)*264 + pl] = h2;
                Bh[(fi*4+3)*264 + pl] = h3;
                Bl[(fi*4  )*264 + pl] = l0;
                Bl[(fi*4+1)*264 + pl] = l1;
                Bl[(fi*4+2)*264 + pl] = l2;
                Bl[(fi*4+3)*264 + pl] = l3;
            }
        }
        __syncthreads();

        #pragma unroll
        for (int ks = 0; ks < 4; ks++){
            const int kb = ks * 8;
            unsigned ah[2][4], al2[2][4];
            #pragma unroll
            for (int mt = 0; mt < 2; mt++){
                int mr = m0w + mt*16 + gid;
                ah[mt][0]  = Ah[mr*36 + kb + tig];
                ah[mt][1]  = Ah[(mr+8)*36 + kb + tig];
                ah[mt][2]  = Ah[mr*36 + kb + tig + 4];
                ah[mt][3]  = Ah[(mr+8)*36 + kb + tig + 4];
                al2[mt][0] = Al[mr*36 + kb + tig];
                al2[mt][1] = Al[(mr+8)*36 + kb + tig];
                al2[mt][2] = Al[mr*36 + kb + tig + 4];
                al2[mt][3] = Al[(mr+8)*36 + kb + tig + 4];
            }
            #pragma unroll
            for (int nt = 0; nt < 8; nt++){
                int nn = n0w + nt*8 + gid;
                unsigned bh0 = Bh[(kb+tig  )*264 + nn];
                unsigned bh1 = Bh[(kb+tig+4)*264 + nn];
                unsigned bl0 = Bl[(kb+tig  )*264 + nn];
                unsigned bl1 = Bl[(kb+tig+4)*264 + nn];
                #pragma unroll
                for (int mt = 0; mt < 2; mt++){
                    mma_bf16(c[mt][nt], ah[mt],  bh0, bh1);
                    mma_bf16(c[mt][nt], ah[mt],  bl0, bl1);
                    mma_bf16(c[mt][nt], al2[mt], bh0, bh1);
                }
            }
        }
    }

    if (MODE == 0 || MODE == 1){
        #pragma unroll
        for (int mt = 0; mt < 2; mt++){
            #pragma unroll
            for (int s = 0; s < 2; s++){
                int rl = m0w + mt*16 + gid + s*8;
                float bv = bias[co0 + rl];
                float* orow = out + ((size_t)bz*C + co0 + rl)*HW + p0;
                #pragma unroll
                for (int nt = 0; nt < 8; nt++){
                    int cs = n0w + nt*8 + tig*2;
                    float v0 = c[mt][nt][s*2+0] + bv;
                    float v1 = c[mt][nt][s*2+1] + bv;
                    if (MODE == 0){
                        v0 = 0.5f*v0*(1.0f + erff(v0*0.70710678f));
                        v1 = 0.5f*v1*(1.0f + erff(v1*0.70710678f));
                    }
                    float2 v = {v0, v1};
                    *(float2*)&orow[cs] = v;
                }
            }
        }
    } else if (MODE == 4){
        const int bb = p0 >> 14;
        const int hw0 = p0 & 16383;
        #pragma unroll
        for (int mt = 0; mt < 2; mt++){
            #pragma unroll
            for (int s = 0; s < 2; s++){
                int rl = m0w + mt*16 + gid + s*8;
                float bv = bias[co0 + rl];
                float* orow = out + ((size_t)bb*C + co0 + rl)*HW + hw0;
                #pragma unroll
                for (int nt = 0; nt < 8; nt++){
                    int cs = n0w + nt*8 + tig*2;
                    float2 v = {c[mt][nt][s*2+0] + bv, c[mt][nt][s*2+1] + bv};
                    *(float2*)&orow[cs] = v;
                }
            }
        }
    } else {
        // modes 2,3: stage transposed [pixel][68] -> conflict-free STS,
        // vectorized LDS.128 reads
        __syncthreads();
        #pragma unroll
        for (int mt = 0; mt < 2; mt++){
            #pragma unroll
            for (int s = 0; s < 2; s++){
                int rl = m0w + mt*16 + gid + s*8;
                float bv;
                if (MODE == 3){
                    int co = co0 + rl;
                    bv = (co < 192) ? qb[co] : (co < 384 ? 0.0f : vb[co - 384]);
                } else {
                    bv = bias[co0 + rl];
                }
                const float* rrow = (MODE == 2)
                    ? (res + ((size_t)bz*C + co0 + rl)*HW + p0) : nullptr;
                #pragma unroll
                for (int nt = 0; nt < 8; nt++){
                    int cs = n0w + nt*8 + tig*2;
                    float v0 = c[mt][nt][s*2+0] + bv;
                    float v1 = c[mt][nt][s*2+1] + bv;
                    if (MODE == 2){
                        float2 rv = *(const float2*)&rrow[cs];
                        v0 += rv.x; v1 += rv.y;
                    }
                    stg[(size_t)cs*68 + rl]       = v0;
                    stg[(size_t)(cs+1)*68 + rl]   = v1;
                }
            }
        }
        __syncthreads();
        const int ldo = (MODE == 3) ? 576 : 192;
        const size_t pbase = (MODE == 3) ? (size_t)p0 : ((size_t)bz*HW + p0);
        #pragma unroll
        for (int r = 0; r < 4; r++){
            int pl = (t >> 2) + r*64;
            int cq = (t & 3) * 16;
            float vals[16];
            const float* rowp = &stg[(size_t)pl*68 + cq];
            *(float4*)&vals[0]  = *(const float4*)&rowp[0];
            *(float4*)&vals[4]  = *(const float4*)&rowp[4];
            *(float4*)&vals[8]  = *(const float4*)&rowp[8];
            *(float4*)&vals[12] = *(const float4*)&rowp[12];
            if (MODE == 2){
                float s = 0.0f, s2 = 0.0f;
                #pragma unroll
                for (int j = 0; j < 16; j++){ s += vals[j]; s2 += vals[j]*vals[j]; }
                s  += __shfl_xor_sync(0xffffffffu, s, 1);
                s  += __shfl_xor_sync(0xffffffffu, s, 2);
                s2 += __shfl_xor_sync(0xffffffffu, s2, 1);
                s2 += __shfl_xor_sync(0xffffffffu, s2, 2);
                if ((t & 3) == 0){
                    size_t px = (size_t)bz*HW + p0 + pl;
                    atomicAdd(&stats[px*2],     s);
                    atomicAdd(&stats[px*2 + 1], s2);
                }
            }
            float* op = out + (pbase + pl)*ldo + co0 + cq;
            *(float4*)&op[0]  = *(float4*)&vals[0];
            *(float4*)&op[4]  = *(float4*)&vals[4];
            *(float4*)&op[8]  = *(float4*)&vals[8];
            *(float4*)&op[12] = *(float4*)&vals[12];
        }
    }
}

// ---------------- fused depthwise 5x5 + 5x5 dil3 (register-tiled) ----------
__global__ void __launch_bounds__(256)
k_dwf(const float* __restrict__ in, const float* __restrict__ w1,
      const float* __restrict__ b1, const float* __restrict__ w2,
      const float* __restrict__ b2, float* __restrict__ out)
{
    __shared__ float s0[48][52];
    __shared__ float s1[44][52];
    __shared__ float wts[52];
    const int plane = blockIdx.y;
    const int c = plane % C;
    const int tile = blockIdx.x;
    const int y0 = (tile >> 2) * 32, x0 = (tile & 3) * 32;
    const int t = threadIdx.x;

    if (t < 25) wts[t] = w1[c*25 + t];
    else if (t < 50) wts[t] = w2[c*25 + t - 25];
    else if (t == 50) wts[50] = b1[c];
    else if (t == 51) wts[51] = b2[c];

    const float* ip = in + ((size_t)plane << 14);
    for (int idx = t; idx < 48*48; idx += 256){
        int yy = idx / 48, xx = idx - yy*48;
        int gy = y0 - 8 + yy, gx = x0 - 8 + xx;
        s0[yy][xx] = ((unsigned)gy < 128u && (unsigned)gx < 128u) ? ip[gy*128+gx] : 0.0f;
    }
    __syncthreads();

    for (int u = t; u < 264; u += 256){
        int r = u / 6, g = u - 6*r;
        int c0 = g * 8;
        float acc[8];
        #pragma unroll
        for (int cc = 0; cc < 8; cc++) acc[cc] = wts[50];
        #pragma unroll
        for (int i = 0; i < 5; i++){
            float row[12];
            *(float4*)&row[0] = *(const float4*)&s0[r+i][c0];
            *(float4*)&row[4] = *(const float4*)&s0[r+i][c0+4];
            *(float4*)&row[8] = *(const float4*)&s0[r+i][c0+8];
            #pragma unroll
            for (int j = 0; j < 5; j++){
                float wv = wts[i*5+j];
                #pragma unroll
                for (int cc = 0; cc < 8; cc++)
                    acc[cc] = fmaf(wv, row[cc+j], acc[cc]);
            }
        }
        int gy = y0 - 6 + r;
        bool rowok = (unsigned)gy < 128u;
        #pragma unroll
        for (int cc = 0; cc < 8; cc++){
            int gx = x0 - 6 + c0 + cc;
            s1[r][c0+cc] = (rowok && (unsigned)gx < 128u) ? acc[cc] : 0.0f;
        }
    }
    __syncthreads();

    {
        int r = t >> 3, c0 = (t & 7) * 4;
        float acc[4];
        #pragma unroll
        for (int cc = 0; cc < 4; cc++) acc[cc] = wts[51];
        #pragma unroll
        for (int i = 0; i < 5; i++){
            float row[16];
            *(float4*)&row[0]  = *(const float4*)&s1[r+3*i][c0];
            *(float4*)&row[4]  = *(const float4*)&s1[r+3*i][c0+4];
            *(float4*)&row[8]  = *(const float4*)&s1[r+3*i][c0+8];
            *(float4*)&row[12] = *(const float4*)&s1[r+3*i][c0+12];
            #pragma unroll
            for (int j = 0; j < 5; j++){
                float wv = wts[25+i*5+j];
                #pragma unroll
                for (int cc = 0; cc < 4; cc++)
                    acc[cc] = fmaf(wv, row[3*j+cc], acc[cc]);
            }
        }
        *(float4*)&out[((size_t)plane << 14) + (y0+r)*128 + x0 + c0] = *(float4*)&acc[0];
    }
}

// ---------------- SwinV2 cosine window attention (tensor-core flash) --------
// fixed-shift softmax in log2 domain; 32-col half-chunks, 2 CTAs/SM
__global__ void __launch_bounds__(256, 2)
k_attn(const float* __restrict__ qkv, const float* __restrict__ bgl,
       const float* __restrict__ lsc, float* __restrict__ out)
{
    extern __shared__ unsigned sm[];
    unsigned* Kh = sm;                     // [16][264]
    unsigned* Kl = Kh + 16*264;
    unsigned* Vh = Kl + 16*264;            // [128][40]
    unsigned* Vl = Vh + 128*40;
    float* qs = (float*)(Vl + 128*40);     // [256]

    const int w = blockIdx.x, h = blockIdx.y, t = threadIdx.x;
    const int b = w >> 6, wy = (w >> 3) & 7, wx = w & 7;
    const int wid = t >> 5, lane = t & 31, gid = lane >> 2, tig = lane & 3;
    const float scale = __expf(fminf(lsc[h], 4.6051702f));
    const size_t pixbase = (size_t)b*HW + (size_t)(wy*16)*128 + wx*16;

    {
        const int tok = t;
        const size_t pp = pixbase + (size_t)(tok >> 4)*128 + (tok & 15);
        const float* qr = qkv + pp*576 + h*32;
        const float* kr = qr + 192;
        float kv[32]; float ssq = 0.0f, ssk = 0.0f;
        #pragma unroll
        for (int d = 0; d < 8; d++){
            float4 q4 = ((const float4*)qr)[d];
            ssq += q4.x*q4.x + q4.y*q4.y + q4.z*q4.z + q4.w*q4.w;
            float4 k4 = ((const float4*)kr)[d];
            kv[4*d]=k4.x; kv[4*d+1]=k4.y; kv[4*d+2]=k4.z; kv[4*d+3]=k4.w;
            ssk += k4.x*k4.x + k4.y*k4.y + k4.z*k4.z + k4.w*k4.w;
        }
        qs[tok] = scale * LOG2E / fmaxf(sqrtf(ssq), 1e-12f);
        float ki = 1.0f / fmaxf(sqrtf(ssk), 1e-12f);
        #pragma unroll
        for (int d2 = 0; d2 < 16; d2++){
            unsigned hh, ll;
            split2(kv[2*d2]*ki, kv[2*d2+1]*ki, hh, ll);
            Kh[d2*264 + tok] = hh;
            Kl[d2*264 + tok] = ll;
        }
    }
    {
        const int t2 = t >> 1, dh = (t & 1) * 16;
        const size_t pa = pixbase + (size_t)((2*t2) >> 4)*128 + ((2*t2) & 15);
        const size_t pb = pixbase + (size_t)((2*t2+1) >> 4)*128 + ((2*t2+1) & 15);
        const float* v0 = qkv + pa*576 + 384 + h*32 + dh;
        const float* v1 = qkv + pb*576 + 384 + h*32 + dh;
        #pragma unroll
        for (int dq = 0; dq < 4; dq++){
            float4 a = ((const float4*)v0)[dq];
            float4 bb = ((const float4*)v1)[dq];
            unsigned hh, ll;
            split2(a.x, bb.x, hh, ll); Vh[t2*40+dh+4*dq+0]=hh; Vl[t2*40+dh+4*dq+0]=ll;
            split2(a.y, bb.y, hh, ll); Vh[t2*40+dh+4*dq+1]=hh; Vl[t2*40+dh+4*dq+1]=ll;
            split2(a.z, bb.z, hh, ll); Vh[t2*40+dh+4*dq+2]=hh; Vl[t2*40+dh+4*dq+2]=ll;
            split2(a.w, bb.w, hh, ll); Vh[t2*40+dh+4*dq+3]=hh; Vl[t2*40+dh+4*dq+3]=ll;
        }
    }
    __syncthreads();

    unsigned qh[2][2][4], ql[2][2][4];
    #pragma unroll
    for (int mt = 0; mt < 2; mt++){
        int r1 = wid*32 + mt*16 + gid, r2 = r1 + 8;
        float s1 = qs[r1], s2 = qs[r2];
        const float* q1 = qkv + (pixbase + (size_t)(r1>>4)*128 + (r1&15))*576 + h*32;
        const float* q2 = qkv + (pixbase + (size_t)(r2>>4)*128 + (r2&15))*576 + h*32;
        #pragma unroll
        for (int ks = 0; ks < 2; ks++){
            float2 e1 = *(const float2*)(q1 + 16*ks + 2*tig);
            float2 e2 = *(const float2*)(q2 + 16*ks + 2*tig);
            float2 f1 = *(const float2*)(q1 + 16*ks + 8 + 2*tig);
            float2 f2 = *(const float2*)(q2 + 16*ks + 8 + 2*tig);
            split2(e1.x*s1, e1.y*s1, qh[mt][ks][0], ql[mt][ks][0]);
            split2(e2.x*s2, e2.y*s2, qh[mt][ks][1], ql[mt][ks][1]);
            split2(f1.x*s1, f1.y*s1, qh[mt][ks][2], ql[mt][ks][2]);
            split2(f2.x*s2, f2.y*s2, qh[mt][ks][3], ql[mt][ks][3]);
        }
    }

    float l[4] = {0,0,0,0};
    float o[2][4][4];
    #pragma unroll
    for (int i=0;i<2;i++) for (int j=0;j<4;j++) for (int q=0;q<4;q++) o[i][j][q]=0.0f;

    const float* bg = bgl + (size_t)h*256*256;

    for (int ch = 0; ch < 8; ch++){
        const int c0 = ch * 32;
        float c[2][4][4];
        #pragma unroll
        for (int i=0;i<2;i++) for (int j=0;j<4;j++) for (int q=0;q<4;q++) c[i][j][q]=0.0f;

        #pragma unroll
        for (int ks = 0; ks < 2; ks++){
            #pragma unroll
            for (int nt = 0; nt < 4; nt++){
                int n = c0 + nt*8 + gid;
                unsigned bh0 = Kh[(8*ks+tig  )*264 + n];
                unsigned bh1 = Kh[(8*ks+tig+4)*264 + n];
                unsigned bl0 = Kl[(8*ks+tig  )*264 + n];
                unsigned bl1 = Kl[(8*ks+tig+4)*264 + n];
                #pragma unroll
                for (int mt = 0; mt < 2; mt++){
                    mma_bf16(c[mt][nt], qh[mt][ks], bh0, bh1);
                    mma_bf16(c[mt][nt], qh[mt][ks], bl0, bl1);
                    mma_bf16(c[mt][nt], ql[mt][ks], bh0, bh1);
                }
            }
        }

        #pragma unroll
        for (int tt = 0; tt < 2; tt++){
            unsigned ph[2][4], pl[2][4];
            #pragma unroll
            for (int mt = 0; mt < 2; mt++){
                int r1 = wid*32 + mt*16 + gid, r2 = r1 + 8;
                int cc0 = c0 + (2*tt)*8 + 2*tig;
                int cc1 = c0 + (2*tt+1)*8 + 2*tig;
                float2 ba = *(const float2*)&bg[(size_t)r1*256 + cc0];
                float2 bb2 = *(const float2*)&bg[(size_t)r2*256 + cc0];
                float2 bc = *(const float2*)&bg[(size_t)r1*256 + cc1];
                float2 bd = *(const float2*)&bg[(size_t)r2*256 + cc1];
                float p0 = fexp2(c[mt][2*tt  ][0] + ba.x);
                float p1 = fexp2(c[mt][2*tt  ][1] + ba.y);
                float p2 = fexp2(c[mt][2*tt  ][2] + bb2.x);
                float p3 = fexp2(c[mt][2*tt  ][3] + bb2.y);
                float p4 = fexp2(c[mt][2*tt+1][0] + bc.x);
                float p5 = fexp2(c[mt][2*tt+1][1] + bc.y);
                float p6 = fexp2(c[mt][2*tt+1][2] + bd.x);
                float p7 = fexp2(c[mt][2*tt+1][3] + bd.y);
                l[2*mt]   += p0 + p1 + p4 + p5;
                l[2*mt+1] += p2 + p3 + p6 + p7;
                split2(p0, p1, ph[mt][0], pl[mt][0]);
                split2(p2, p3, ph[mt][1], pl[mt][1]);
                split2(p4, p5, ph[mt][2], pl[mt][2]);
                split2(p6, p7, ph[mt][3], pl[mt][3]);
            }
            const int base = (c0 + 16*tt) >> 1;
            #pragma unroll
            for (int nt2 = 0; nt2 < 4; nt2++){
                int dcol = nt2*8 + gid;
                unsigned vh0 = Vh[(base+tig  )*40 + dcol];
                unsigned vh1 = Vh[(base+tig+4)*40 + dcol];
                unsigned vl0 = Vl[(base+tig  )*40 + dcol];
                unsigned vl1 = Vl[(base+tig+4)*40 + dcol];
                #pragma unroll
                for (int mt = 0; mt < 2; mt++){
                    mma_bf16(o[mt][nt2], ph[mt], vh0, vh1);
                    mma_bf16(o[mt][nt2], ph[mt], vl0, vl1);
                    mma_bf16(o[mt][nt2], pl[mt], vh0, vh1);
                }
            }
        }
    }

    #pragma unroll
    for (int q = 0; q < 4; q++){
        l[q] += __shfl_xor_sync(0xffffffffu, l[q], 1);
        l[q] += __shfl_xor_sync(0xffffffffu, l[q], 2);
        l[q] = 1.0f / l[q];
    }
    #pragma unroll
    for (int mt = 0; mt < 2; mt++){
        int r1 = wid*32 + mt*16 + gid, r2 = r1 + 8;
        float* o1 = out + (pixbase + (size_t)(r1>>4)*128 + (r1&15))*192 + h*32;
        float* o2 = out + (pixbase + (size_t)(r2>>4)*128 + (r2&15))*192 + h*32;
        #pragma unroll
        for (int nt2 = 0; nt2 < 4; nt2++){
            int dc = nt2*8 + 2*tig;
            float2 v1 = { o[mt][nt2][0]*l[2*mt],   o[mt][nt2][1]*l[2*mt] };
            float2 v2 = { o[mt][nt2][2]*l[2*mt+1], o[mt][nt2][3]*l[2*mt+1] };
            *(float2*)(o1 + dc) = v1;
            *(float2*)(o2 + dc) = v2;
        }
    }
}

// ---------------------------------------------------------------------------
extern "C" void kernel_launch(void* const* d_in, const int* in_sizes, int n_in,
                              void* d_out, int out_size)
{
    const float* x      = (const float*)d_in[0];
    const float* p1_w   = (const float*)d_in[1];
    const float* p1_b   = (const float*)d_in[2];
    const float* pw_w   = (const float*)d_in[3];
    const float* pw_b   = (const float*)d_in[4];
    const float* dw_w   = (const float*)d_in[5];
    const float* dw_b   = (const float*)d_in[6];
    const float* dd_w   = (const float*)d_in[7];
    const float* dd_b   = (const float*)d_in[8];
    const float* p2_w   = (const float*)d_in[9];
    const float* p2_b   = (const float*)d_in[10];
    const float* ln_g   = (const float*)d_in[11];
    const float* ln_b   = (const float*)d_in[12];
    const float* qkv_w  = (const float*)d_in[13];
    const float* q_bias = (const float*)d_in[14];
    const float* v_bias = (const float*)d_in[15];
    const float* lsc    = (const float*)d_in[16];
    const float* cpb_w1 = (const float*)d_in[17];
    const float* cpb_b1 = (const float*)d_in[18];
    const float* cpb_w2 = (const float*)d_in[19];
    const float* proj_w = (const float*)d_in[20];
    const float* proj_b = (const float*)d_in[21];
    float* outp = (float*)d_out;

    float *gy, *ga, *gb, *gq, *gt, *gbias, *gst;
    cudaGetSymbolAddress((void**)&gy, g_y);
    cudaGetSymbolAddress((void**)&ga, g_a);
    cudaGetSymbolAddress((void**)&gb, g_b);
    cudaGetSymbolAddress((void**)&gq, g_qkv);
    cudaGetSymbolAddress((void**)&gt, g_tbl);
    cudaGetSymbolAddress((void**)&gbias, g_bias);
    cudaGetSymbolAddress((void**)&gst, g_stats);

    const int ATTN_SMEM = (2*16*264 + 2*128*40 + 256) * 4;
    cudaFuncSetAttribute(k_attn, cudaFuncAttributeMaxDynamicSharedMemorySize, ATTN_SMEM);
    const int GEMM_SMEM_LOAD = (2*64*36 + 2*32*264) * 4;         // 86016
    const int GEMM_SMEM_M3   = GEMM_SMEM_LOAD + 512*4;           // + sstat = 88064
    cudaFuncSetAttribute(k_gemm<0>, cudaFuncAttributeMaxDynamicSharedMemorySize, GEMM_SMEM_LOAD);
    cudaFuncSetAttribute(k_gemm<1>, cudaFuncAttributeMaxDynamicSharedMemorySize, GEMM_SMEM_LOAD);
    cudaFuncSetAttribute(k_gemm<2>, cudaFuncAttributeMaxDynamicSharedMemorySize, GEMM_SMEM_LOAD);
    cudaFuncSetAttribute(k_gemm<3>, cudaFuncAttributeMaxDynamicSharedMemorySize, GEMM_SMEM_M3);
    cudaFuncSetAttribute(k_gemm<4>, cudaFuncAttributeMaxDynamicSharedMemorySize, GEMM_SMEM_LOAD);

    dim3 gNCHW(HW/256, 3, BATCH);

    // zero LN partial sums (accumulated atomically by p2 epilogue)
    cudaMemsetAsync(gst, 0, (size_t)NPIX*2*sizeof(float));

    // CPB bias table + expansion (independent of main chain)
    k_cpb<<<961, 128>>>(cpb_w1, cpb_b1, cpb_w2, gt);
    k_bias<<<dim3(256, NH), 256>>>(gt, lsc, gbias);

    // VAB conv block
    k_gemm<0><<<gNCHW, 256, GEMM_SMEM_LOAD>>>(x,  p1_w, p1_b, nullptr, nullptr, nullptr, nullptr, gy, gst);
    k_gemm<1><<<gNCHW, 256, GEMM_SMEM_LOAD>>>(gy, pw_w, pw_b, nullptr, nullptr, nullptr, nullptr, ga, gst);
    k_dwf<<<dim3(16, BATCH*C), 256>>>(ga, dw_w, dw_b, dd_w, dd_b, gb);
    k_gemm<2><<<gNCHW, 256, GEMM_SMEM_LOAD>>>(gy, p2_w, p2_b, gb, x, nullptr, nullptr, ga, gst);

    // QKV projection with fused LayerNorm (stats accumulated by p2)
    k_gemm<3><<<dim3(NPIX/256, 9), 256, GEMM_SMEM_M3>>>(ga, qkv_w, ln_b, gst, ln_g, q_bias, v_bias, gq, gst);

    // Tensor-core windowed attention -> BHWC in gy
    k_attn<<<dim3(NWIN, NH), 256, ATTN_SMEM>>>(gq, gbias, lsc, gy);

    // Output projection -> NCHW d_out
    k_gemm<4><<<dim3(NPIX/256, 3), 256, GEMM_SMEM_LOAD>>>(gy, proj_w, proj_b, nullptr, nullptr, nullptr, nullptr, outp, gst);
}

// round 15
// speedup vs baseline: 1.1348x; 1.1348x over previous
#include <cuda_runtime.h>
#include <cuda_bf16.h>
#include <math.h>

#define BATCH 4
#define C 192
#define HW 16384            // 128*128
#define NPIX (BATCH*HW)     // 65536
#define NH 6
#define HD 32
#define NWIN 256
#define NTOK 256
#define LOG2E 1.44269504088896f

// ---------------- scratch (device globals; no allocations allowed) ----------
__device__ float g_y[BATCH*C*HW];
__device__ float g_a[BATCH*C*HW];
__device__ float g_b[BATCH*C*HW];
__device__ float g_qkv[(size_t)NPIX*576];
__device__ float g_tbl[961*NH];
__device__ float g_bias[NH*256*256];       // expanded CPB bias (log2-domain, pre-shifted)
__device__ float g_stats[NPIX*2];          // per-pixel LN partial (S, S2)

// ---------------- fast exp2 on the FMA pipe (input already log2-domain) -----
__device__ __forceinline__ float fexp2(float z){
    z = fmaxf(z, -126.0f);
    float mz = z + 12582912.0f;
    int   iz = __float_as_int(mz);
    float f  = z - (mz - 12582912.0f);
    float p  = 1.0f + f*(0.6931471806f + f*(0.2402265070f + f*(0.0555041087f
              + f*(0.0096181291f + f*0.0013333558f))));
    return __int_as_float(__float_as_int(p) + (iz << 23));
}

// ---------------- bf16 split helpers ---------------------------------------
__device__ __forceinline__ unsigned packbf(float lo, float hi){
    unsigned r;
    asm("cvt.rn.bf16x2.f32 %0, %1, %2;" : "=r"(r) : "f"(hi), "f"(lo));
    return r;
}
__device__ __forceinline__ float bflo(unsigned u){ return __uint_as_float(u << 16); }
__device__ __forceinline__ float bfhi(unsigned u){ return __uint_as_float(u & 0xffff0000u); }

__device__ __forceinline__ void split2(float a, float b, unsigned& h, unsigned& l){
    h = packbf(a, b);
    l = packbf(a - bflo(h), b - bfhi(h));
}

__device__ __forceinline__ void mma_bf16(float c[4], const unsigned a[4],
                                         unsigned b0, unsigned b1){
    asm("mma.sync.aligned.m16n8k16.row.col.f32.bf16.bf16.f32 "
        "{%0,%1,%2,%3},{%4,%5,%6,%7},{%8,%9},{%0,%1,%2,%3};"
        : "+f"(c[0]), "+f"(c[1]), "+f"(c[2]), "+f"(c[3])
        : "r"(a[0]), "r"(a[1]), "r"(a[2]), "r"(a[3]), "r"(b0), "r"(b1));
}

// ---------------- CPB MLP table --------------------------------------------
__global__ void k_cpb(const float* __restrict__ w1, const float* __restrict__ b1,
                      const float* __restrict__ w2, float* __restrict__ tbl)
{
    int r = blockIdx.x;
    int t = threadIdx.x;
    float dy = (float)(r / 31) - 15.0f;
    float dx = (float)(r % 31) - 15.0f;
    float u0 = dy / 15.0f * 8.0f, u1 = dx / 15.0f * 8.0f;
    float t0 = copysignf(log2f(fabsf(u0) + 1.0f) * (1.0f/3.0f), u0);
    float t1 = copysignf(log2f(fabsf(u1) + 1.0f) * (1.0f/3.0f), u1);
    float acc[6] = {0,0,0,0,0,0};
    for (int u = t; u < 512; u += 128){
        float hv = fmaxf(w1[2*u]*t0 + w1[2*u+1]*t1 + b1[u], 0.0f);
        #pragma unroll
        for (int h = 0; h < 6; h++) acc[h] += hv * w2[h*512 + u];
    }
    __shared__ float red[6][128];
    #pragma unroll
    for (int h = 0; h < 6; h++) red[h][t] = acc[h];
    __syncthreads();
    for (int off = 64; off > 0; off >>= 1){
        if (t < off){
            #pragma unroll
            for (int h = 0; h < 6; h++) red[h][t] += red[h][t+off];
        }
        __syncthreads();
    }
    if (t < 6){
        float v = red[t][0];
        tbl[r*6 + t] = 16.0f / (1.0f + expf(-v));
    }
}

// ---------------- expand CPB bias to [h][256][256], log2 domain, -m_h -------
__global__ void k_bias(const float* __restrict__ tbl, const float* __restrict__ lsc,
                       float* __restrict__ bg)
{
    int r = blockIdx.x, h = blockIdx.y, c = threadIdx.x;
    int iy = r >> 4, ix = r & 15, my = c >> 4, mx = c & 15;
    int idx = (iy - my + 15)*31 + (ix - mx + 15);
    float scale = __expf(fminf(lsc[h], 4.6051702f));
    bg[((size_t)h*256 + r)*256 + c] = (tbl[idx*6 + h] - (scale + 16.0f)) * LOG2E;
}

// ---------------- tensor-core GEMM (bf16 hi/lo split, fp32 accum) ----------
// MODE 0: p1; 1: pw; 2: p2 (gate+res->BHWC, accumulates LN stats);
// MODE 3: qkv (inline LN from raw sums); 4: proj->NCHW
// B smem stride 264 -> conflict-free fragment loads. Epilogue stage (modes
// 2,3) is [pixel][68] -> conflict-free stores, vectorized reads.
template<int MODE>
__global__ void __launch_bounds__(256, 2)
k_gemm(const float* __restrict__ X, const float* __restrict__ W,
       const float* __restrict__ bias, const float* __restrict__ X2,
       const float* __restrict__ res, const float* __restrict__ qb,
       const float* __restrict__ vb, float* __restrict__ out,
       float* __restrict__ stats)
{
    // MODE 3 reinterprets: bias = ln_b, res = ln_g, X2 = raw stats (S, S2)
    extern __shared__ unsigned smem_u[];
    unsigned* Ah = smem_u;                  // 64*20
    unsigned* Al = Ah + 64*20;
    unsigned* Bh = Al + 64*20;              // 16*264
    unsigned* Bl = Bh + 16*264;
    float* sstat = (float*)(Bl + 16*264);   // mode 3: [256]*(mu,rs) @ 44032 B
    float* stg = (float*)smem_u;            // overlay (modes 2,3 epilogue): [256][68]

    const int t = threadIdx.x;
    const int wid = t >> 5, lane = t & 31;
    const int gid = lane >> 2, tig = lane & 3;
    const int m0w = (wid & 1) * 32;
    const int n0w = (wid >> 1) * 64;

    const int p0  = blockIdx.x * 256;
    const int co0 = blockIdx.y * 64;
    const int bz  = (MODE <= 2) ? blockIdx.z : 0;

    const float* Xb  = (MODE <= 2) ? (X + (size_t)bz*C*HW) : X;
    const float* X2b = (MODE == 2) ? (X2 + (size_t)bz*C*HW) : nullptr;

    float c[2][8][4];
    #pragma unroll
    for (int i = 0; i < 2; i++)
        #pragma unroll
        for (int j = 0; j < 8; j++)
            #pragma unroll
            for (int q = 0; q < 4; q++) c[i][j][q] = 0.0f;

    const int ar  = t >> 2;
    const int akq = (t & 3) * 8;

    if (MODE == 3){
        // per-pixel LN stats from raw sums
        float2 ssum = *(const float2*)&X2[(size_t)(p0 + t)*2];
        float mu = ssum.x * (1.0f/192.0f);
        float var = ssum.y * (1.0f/192.0f) - mu*mu;
        float rs = rsqrtf(var + 1e-5f);
        sstat[2*t] = mu; sstat[2*t+1] = rs;
    }

    for (int kc = 0; kc < 6; kc++){
        const int k0 = kc * 32;
        __syncthreads();
        {
            const float* wp = &W[(size_t)(co0 + ar)*192 + k0 + akq];
            float4 w0 = *(const float4*)wp;
            float4 w1 = *(const float4*)(wp + 4);
            uint4 h, l;
            split2(w0.x, w0.y, h.x, l.x);
            split2(w0.z, w0.w, h.y, l.y);
            split2(w1.x, w1.y, h.z, l.z);
            split2(w1.z, w1.w, h.w, l.w);
            *(uint4*)&Ah[ar*20 + akq/2] = h;
            *(uint4*)&Al[ar*20 + akq/2] = l;
        }
        if (MODE <= 2){
            const int bp  = (t & 63) * 4;
            const int bk2 = t >> 6;
            #pragma unroll
            for (int r = 0; r < 4; r++){
                int k2i = bk2 + r*4;
                int k = k0 + k2i*2;
                const float* xr = Xb + (size_t)k*HW + p0 + bp;
                float4 e = *(const float4*)xr;
                float4 o = *(const float4*)(xr + HW);
                if (MODE == 2){
                    const float* mr = X2b + (size_t)k*HW + p0 + bp;
                    float4 m1 = *(const float4*)mr;
                    float4 m2 = *(const float4*)(mr + HW);
                    e.x*=m1.x; e.y*=m1.y; e.z*=m1.z; e.w*=m1.w;
                    o.x*=m2.x; o.y*=m2.y; o.z*=m2.z; o.w*=m2.w;
                }
                uint4 h, l;
                split2(e.x, o.x, h.x, l.x);
                split2(e.y, o.y, h.y, l.y);
                split2(e.z, o.z, h.z, l.z);
                split2(e.w, o.w, h.w, l.w);
                *(uint4*)&Bh[k2i*264 + bp] = h;
                *(uint4*)&Bl[k2i*264 + bp] = l;
            }
        } else {
            const int fi = t & 7;
            const int k = k0 + fi*4;
            float4 gv, bv4;
            if (MODE == 3){
                gv  = *(const float4*)&res[k];     // ln gamma
                bv4 = *(const float4*)&bias[k];    // ln beta
            }
            #pragma unroll
            for (int r = 0; r < 8; r++){
                int pl = (t >> 3) + r*32;
                float4 v = *(const float4*)&Xb[(size_t)(p0 + pl)*192 + k];
                if (MODE == 3){
                    float2 st = *(const float2*)&sstat[2*pl];
                    v.x = (v.x - st.x)*st.y*gv.x + bv4.x;
                    v.y = (v.y - st.x)*st.y*gv.y + bv4.y;
                    v.z = (v.z - st.x)*st.y*gv.z + bv4.z;
                    v.w = (v.w - st.x)*st.y*gv.w + bv4.w;
                }
                unsigned h0, l0, h1, l1;
                split2(v.x, v.y, h0, l0);
                split2(v.z, v.w, h1, l1);
                Bh[(fi*2  )*264 + pl] = h0;
                Bh[(fi*2+1)*264 + pl] = h1;
                Bl[(fi*2  )*264 + pl] = l0;
                Bl[(fi*2+1)*264 + pl] = l1;
            }
        }
        __syncthreads();

        #pragma unroll
        for (int ks = 0; ks < 2; ks++){
            const int kb = ks * 8;
            unsigned ah[2][4], al2[2][4];
            #pragma unroll
            for (int mt = 0; mt < 2; mt++){
                int mr = m0w + mt*16 + gid;
                ah[mt][0]  = Ah[mr*20 + kb + tig];
                ah[mt][1]  = Ah[(mr+8)*20 + kb + tig];
                ah[mt][2]  = Ah[mr*20 + kb + tig + 4];
                ah[mt][3]  = Ah[(mr+8)*20 + kb + tig + 4];
                al2[mt][0] = Al[mr*20 + kb + tig];
                al2[mt][1] = Al[(mr+8)*20 + kb + tig];
                al2[mt][2] = Al[mr*20 + kb + tig + 4];
                al2[mt][3] = Al[(mr+8)*20 + kb + tig + 4];
            }
            #pragma unroll
            for (int nt = 0; nt < 8; nt++){
                int nn = n0w + nt*8 + gid;
                unsigned bh0 = Bh[(kb+tig  )*264 + nn];
                unsigned bh1 = Bh[(kb+tig+4)*264 + nn];
                unsigned bl0 = Bl[(kb+tig  )*264 + nn];
                unsigned bl1 = Bl[(kb+tig+4)*264 + nn];
                #pragma unroll
                for (int mt = 0; mt < 2; mt++){
                    mma_bf16(c[mt][nt], ah[mt],  bh0, bh1);
                    mma_bf16(c[mt][nt], ah[mt],  bl0, bl1);
                    mma_bf16(c[mt][nt], al2[mt], bh0, bh1);
                }
            }
        }
    }

    if (MODE == 0 || MODE == 1){
        #pragma unroll
        for (int mt = 0; mt < 2; mt++){
            #pragma unroll
            for (int s = 0; s < 2; s++){
                int rl = m0w + mt*16 + gid + s*8;
                float bv = bias[co0 + rl];
                float* orow = out + ((size_t)bz*C + co0 + rl)*HW + p0;
                #pragma unroll
                for (int nt = 0; nt < 8; nt++){
                    int cs = n0w + nt*8 + tig*2;
                    float v0 = c[mt][nt][s*2+0] + bv;
                    float v1 = c[mt][nt][s*2+1] + bv;
                    if (MODE == 0){
                        v0 = 0.5f*v0*(1.0f + erff(v0*0.70710678f));
                        v1 = 0.5f*v1*(1.0f + erff(v1*0.70710678f));
                    }
                    float2 v = {v0, v1};
                    *(float2*)&orow[cs] = v;
                }
            }
        }
    } else if (MODE == 4){
        const int bb = p0 >> 14;
        const int hw0 = p0 & 16383;
        #pragma unroll
        for (int mt = 0; mt < 2; mt++){
            #pragma unroll
            for (int s = 0; s < 2; s++){
                int rl = m0w + mt*16 + gid + s*8;
                float bv = bias[co0 + rl];
                float* orow = out + ((size_t)bb*C + co0 + rl)*HW + hw0;
                #pragma unroll
                for (int nt = 0; nt < 8; nt++){
                    int cs = n0w + nt*8 + tig*2;
                    float2 v = {c[mt][nt][s*2+0] + bv, c[mt][nt][s*2+1] + bv};
                    *(float2*)&orow[cs] = v;
                }
            }
        }
    } else {
        // modes 2,3: stage transposed [pixel][68] -> conflict-free STS,
        // vectorized LDS.128 reads
        __syncthreads();
        #pragma unroll
        for (int mt = 0; mt < 2; mt++){
            #pragma unroll
            for (int s = 0; s < 2; s++){
                int rl = m0w + mt*16 + gid + s*8;
                float bv;
                if (MODE == 3){
                    int co = co0 + rl;
                    bv = (co < 192) ? qb[co] : (co < 384 ? 0.0f : vb[co - 384]);
                } else {
                    bv = bias[co0 + rl];
                }
                const float* rrow = (MODE == 2)
                    ? (res + ((size_t)bz*C + co0 + rl)*HW + p0) : nullptr;
                #pragma unroll
                for (int nt = 0; nt < 8; nt++){
                    int cs = n0w + nt*8 + tig*2;
                    float v0 = c[mt][nt][s*2+0] + bv;
                    float v1 = c[mt][nt][s*2+1] + bv;
                    if (MODE == 2){
                        float2 rv = *(const float2*)&rrow[cs];
                        v0 += rv.x; v1 += rv.y;
                    }
                    stg[(size_t)cs*68 + rl]       = v0;
                    stg[(size_t)(cs+1)*68 + rl]   = v1;
                }
            }
        }
        __syncthreads();
        const int ldo = (MODE == 3) ? 576 : 192;
        const size_t pbase = (MODE == 3) ? (size_t)p0 : ((size_t)bz*HW + p0);
        #pragma unroll
        for (int r = 0; r < 4; r++){
            int pl = (t >> 2) + r*64;
            int cq = (t & 3) * 16;
            float vals[16];
            const float* rowp = &stg[(size_t)pl*68 + cq];
            *(float4*)&vals[0]  = *(const float4*)&rowp[0];
            *(float4*)&vals[4]  = *(const float4*)&rowp[4];
            *(float4*)&vals[8]  = *(const float4*)&rowp[8];
            *(float4*)&vals[12] = *(const float4*)&rowp[12];
            if (MODE == 2){
                float s = 0.0f, s2 = 0.0f;
                #pragma unroll
                for (int j = 0; j < 16; j++){ s += vals[j]; s2 += vals[j]*vals[j]; }
                s  += __shfl_xor_sync(0xffffffffu, s, 1);
                s  += __shfl_xor_sync(0xffffffffu, s, 2);
                s2 += __shfl_xor_sync(0xffffffffu, s2, 1);
                s2 += __shfl_xor_sync(0xffffffffu, s2, 2);
                if ((t & 3) == 0){
                    size_t px = (size_t)bz*HW + p0 + pl;
                    atomicAdd(&stats[px*2],     s);
                    atomicAdd(&stats[px*2 + 1], s2);
                }
            }
            float* op = out + (pbase + pl)*ldo + co0 + cq;
            *(float4*)&op[0]  = *(float4*)&vals[0];
            *(float4*)&op[4]  = *(float4*)&vals[4];
            *(float4*)&op[8]  = *(float4*)&vals[8];
            *(float4*)&op[12] = *(float4*)&vals[12];
        }
    }
}

// ---------------- fused depthwise 5x5 + 5x5 dil3 (register-tiled) ----------
__global__ void __launch_bounds__(256)
k_dwf(const float* __restrict__ in, const float* __restrict__ w1,
      const float* __restrict__ b1, const float* __restrict__ w2,
      const float* __restrict__ b2, float* __restrict__ out)
{
    __shared__ float s0[48][52];
    __shared__ float s1[44][52];
    __shared__ float wts[52];
    const int plane = blockIdx.y;
    const int c = plane % C;
    const int tile = blockIdx.x;
    const int y0 = (tile >> 2) * 32, x0 = (tile & 3) * 32;
    const int t = threadIdx.x;

    if (t < 25) wts[t] = w1[c*25 + t];
    else if (t < 50) wts[t] = w2[c*25 + t - 25];
    else if (t == 50) wts[50] = b1[c];
    else if (t == 51) wts[51] = b2[c];

    const float* ip = in + ((size_t)plane << 14);
    for (int idx = t; idx < 48*48; idx += 256){
        int yy = idx / 48, xx = idx - yy*48;
        int gy = y0 - 8 + yy, gx = x0 - 8 + xx;
        s0[yy][xx] = ((unsigned)gy < 128u && (unsigned)gx < 128u) ? ip[gy*128+gx] : 0.0f;
    }
    __syncthreads();

    for (int u = t; u < 264; u += 256){
        int r = u / 6, g = u - 6*r;
        int c0 = g * 8;
        float acc[8];
        #pragma unroll
        for (int cc = 0; cc < 8; cc++) acc[cc] = wts[50];
        #pragma unroll
        for (int i = 0; i < 5; i++){
            float row[12];
            *(float4*)&row[0] = *(const float4*)&s0[r+i][c0];
            *(float4*)&row[4] = *(const float4*)&s0[r+i][c0+4];
            *(float4*)&row[8] = *(const float4*)&s0[r+i][c0+8];
            #pragma unroll
            for (int j = 0; j < 5; j++){
                float wv = wts[i*5+j];
                #pragma unroll
                for (int cc = 0; cc < 8; cc++)
                    acc[cc] = fmaf(wv, row[cc+j], acc[cc]);
            }
        }
        int gy = y0 - 6 + r;
        bool rowok = (unsigned)gy < 128u;
        #pragma unroll
        for (int cc = 0; cc < 8; cc++){
            int gx = x0 - 6 + c0 + cc;
            s1[r][c0+cc] = (rowok && (unsigned)gx < 128u) ? acc[cc] : 0.0f;
        }
    }
    __syncthreads();

    {
        int r = t >> 3, c0 = (t & 7) * 4;
        float acc[4];
        #pragma unroll
        for (int cc = 0; cc < 4; cc++) acc[cc] = wts[51];
        #pragma unroll
        for (int i = 0; i < 5; i++){
            float row[16];
            *(float4*)&row[0]  = *(const float4*)&s1[r+3*i][c0];
            *(float4*)&row[4]  = *(const float4*)&s1[r+3*i][c0+4];
            *(float4*)&row[8]  = *(const float4*)&s1[r+3*i][c0+8];
            *(float4*)&row[12] = *(const float4*)&s1[r+3*i][c0+12];
            #pragma unroll
            for (int j = 0; j < 5; j++){
                float wv = wts[25+i*5+j];
                #pragma unroll
                for (int cc = 0; cc < 4; cc++)
                    acc[cc] = fmaf(wv, row[3*j+cc], acc[cc]);
            }
        }
        *(float4*)&out[((size_t)plane << 14) + (y0+r)*128 + x0 + c0] = *(float4*)&acc[0];
    }
}

// ---------------- SwinV2 cosine window attention (tensor-core flash) --------
// fixed-shift softmax in log2 domain; 32-col half-chunks, 2 CTAs/SM
__global__ void __launch_bounds__(256, 2)
k_attn(const float* __restrict__ qkv, const float* __restrict__ bgl,
       const float* __restrict__ lsc, float* __restrict__ out)
{
    extern __shared__ unsigned sm[];
    unsigned* Kh = sm;                     // [16][264]
    unsigned* Kl = Kh + 16*264;
    unsigned* Vh = Kl + 16*264;            // [128][40]
    unsigned* Vl = Vh + 128*40;
    float* qs = (float*)(Vl + 128*40);     // [256]

    const int w = blockIdx.x, h = blockIdx.y, t = threadIdx.x;
    const int b = w >> 6, wy = (w >> 3) & 7, wx = w & 7;
    const int wid = t >> 5, lane = t & 31, gid = lane >> 2, tig = lane & 3;
    const float scale = __expf(fminf(lsc[h], 4.6051702f));
    const size_t pixbase = (size_t)b*HW + (size_t)(wy*16)*128 + wx*16;

    {
        const int tok = t;
        const size_t pp = pixbase + (size_t)(tok >> 4)*128 + (tok & 15);
        const float* qr = qkv + pp*576 + h*32;
        const float* kr = qr + 192;
        float kv[32]; float ssq = 0.0f, ssk = 0.0f;
        #pragma unroll
        for (int d = 0; d < 8; d++){
            float4 q4 = ((const float4*)qr)[d];
            ssq += q4.x*q4.x + q4.y*q4.y + q4.z*q4.z + q4.w*q4.w;
            float4 k4 = ((const float4*)kr)[d];
            kv[4*d]=k4.x; kv[4*d+1]=k4.y; kv[4*d+2]=k4.z; kv[4*d+3]=k4.w;
            ssk += k4.x*k4.x + k4.y*k4.y + k4.z*k4.z + k4.w*k4.w;
        }
        qs[tok] = scale * LOG2E / fmaxf(sqrtf(ssq), 1e-12f);
        float ki = 1.0f / fmaxf(sqrtf(ssk), 1e-12f);
        #pragma unroll
        for (int d2 = 0; d2 < 16; d2++){
            unsigned hh, ll;
            split2(kv[2*d2]*ki, kv[2*d2+1]*ki, hh, ll);
            Kh[d2*264 + tok] = hh;
            Kl[d2*264 + tok] = ll;
        }
    }
    {
        const int t2 = t >> 1, dh = (t & 1) * 16;
        const size_t pa = pixbase + (size_t)((2*t2) >> 4)*128 + ((2*t2) & 15);
        const size_t pb = pixbase + (size_t)((2*t2+1) >> 4)*128 + ((2*t2+1) & 15);
        const float* v0 = qkv + pa*576 + 384 + h*32 + dh;
        const float* v1 = qkv + pb*576 + 384 + h*32 + dh;
        #pragma unroll
        for (int dq = 0; dq < 4; dq++){
            float4 a = ((const float4*)v0)[dq];
            float4 bb = ((const float4*)v1)[dq];
            unsigned hh, ll;
            split2(a.x, bb.x, hh, ll); Vh[t2*40+dh+4*dq+0]=hh; Vl[t2*40+dh+4*dq+0]=ll;
            split2(a.y, bb.y, hh, ll); Vh[t2*40+dh+4*dq+1]=hh; Vl[t2*40+dh+4*dq+1]=ll;
            split2(a.z, bb.z, hh, ll); Vh[t2*40+dh+4*dq+2]=hh; Vl[t2*40+dh+4*dq+2]=ll;
            split2(a.w, bb.w, hh, ll); Vh[t2*40+dh+4*dq+3]=hh; Vl[t2*40+dh+4*dq+3]=ll;
        }
    }
    __syncthreads();

    unsigned qh[2][2][4], ql[2][2][4];
    #pragma unroll
    for (int mt = 0; mt < 2; mt++){
        int r1 = wid*32 + mt*16 + gid, r2 = r1 + 8;
        float s1 = qs[r1], s2 = qs[r2];
        const float* q1 = qkv + (pixbase + (size_t)(r1>>4)*128 + (r1&15))*576 + h*32;
        const float* q2 = qkv + (pixbase + (size_t)(r2>>4)*128 + (r2&15))*576 + h*32;
        #pragma unroll
        for (int ks = 0; ks < 2; ks++){
            float2 e1 = *(const float2*)(q1 + 16*ks + 2*tig);
            float2 e2 = *(const float2*)(q2 + 16*ks + 2*tig);
            float2 f1 = *(const float2*)(q1 + 16*ks + 8 + 2*tig);
            float2 f2 = *(const float2*)(q2 + 16*ks + 8 + 2*tig);
            split2(e1.x*s1, e1.y*s1, qh[mt][ks][0], ql[mt][ks][0]);
            split2(e2.x*s2, e2.y*s2, qh[mt][ks][1], ql[mt][ks][1]);
            split2(f1.x*s1, f1.y*s1, qh[mt][ks][2], ql[mt][ks][2]);
            split2(f2.x*s2, f2.y*s2, qh[mt][ks][3], ql[mt][ks][3]);
        }
    }

    float l[4] = {0,0,0,0};
    float o[2][4][4];
    #pragma unroll
    for (int i=0;i<2;i++) for (int j=0;j<4;j++) for (int q=0;q<4;q++) o[i][j][q]=0.0f;

    const float* bg = bgl + (size_t)h*256*256;

    for (int ch = 0; ch < 8; ch++){
        const int c0 = ch * 32;
        float c[2][4][4];
        #pragma unroll
        for (int i=0;i<2;i++) for (int j=0;j<4;j++) for (int q=0;q<4;q++) c[i][j][q]=0.0f;

        #pragma unroll
        for (int ks = 0; ks < 2; ks++){
            #pragma unroll
            for (int nt = 0; nt < 4; nt++){
                int n = c0 + nt*8 + gid;
                unsigned bh0 = Kh[(8*ks+tig  )*264 + n];
                unsigned bh1 = Kh[(8*ks+tig+4)*264 + n];
                unsigned bl0 = Kl[(8*ks+tig  )*264 + n];
                unsigned bl1 = Kl[(8*ks+tig+4)*264 + n];
                #pragma unroll
                for (int mt = 0; mt < 2; mt++){
                    mma_bf16(c[mt][nt], qh[mt][ks], bh0, bh1);
                    mma_bf16(c[mt][nt], qh[mt][ks], bl0, bl1);
                    mma_bf16(c[mt][nt], ql[mt][ks], bh0, bh1);
                }
            }
        }

        #pragma unroll
        for (int tt = 0; tt < 2; tt++){
            unsigned ph[2][4], pl[2][4];
            #pragma unroll
            for (int mt = 0; mt < 2; mt++){
                int r1 = wid*32 + mt*16 + gid, r2 = r1 + 8;
                int cc0 = c0 + (2*tt)*8 + 2*tig;
                int cc1 = c0 + (2*tt+1)*8 + 2*tig;
                float2 ba = *(const float2*)&bg[(size_t)r1*256 + cc0];
                float2 bb2 = *(const float2*)&bg[(size_t)r2*256 + cc0];
                float2 bc = *(const float2*)&bg[(size_t)r1*256 + cc1];
                float2 bd = *(const float2*)&bg[(size_t)r2*256 + cc1];
                float p0 = fexp2(c[mt][2*tt  ][0] + ba.x);
                float p1 = fexp2(c[mt][2*tt  ][1] + ba.y);
                float p2 = fexp2(c[mt][2*tt  ][2] + bb2.x);
                float p3 = fexp2(c[mt][2*tt  ][3] + bb2.y);
                float p4 = fexp2(c[mt][2*tt+1][0] + bc.x);
                float p5 = fexp2(c[mt][2*tt+1][1] + bc.y);
                float p6 = fexp2(c[mt][2*tt+1][2] + bd.x);
                float p7 = fexp2(c[mt][2*tt+1][3] + bd.y);
                l[2*mt]   += p0 + p1 + p4 + p5;
                l[2*mt+1] += p2 + p3 + p6 + p7;
                split2(p0, p1, ph[mt][0], pl[mt][0]);
                split2(p2, p3, ph[mt][1], pl[mt][1]);
                split2(p4, p5, ph[mt][2], pl[mt][2]);
                split2(p6, p7, ph[mt][3], pl[mt][3]);
            }
            const int base = (c0 + 16*tt) >> 1;
            #pragma unroll
            for (int nt2 = 0; nt2 < 4; nt2++){
                int dcol = nt2*8 + gid;
                unsigned vh0 = Vh[(base+tig  )*40 + dcol];
                unsigned vh1 = Vh[(base+tig+4)*40 + dcol];
                unsigned vl0 = Vl[(base+tig  )*40 + dcol];
                unsigned vl1 = Vl[(base+tig+4)*40 + dcol];
                #pragma unroll
                for (int mt = 0; mt < 2; mt++){
                    mma_bf16(o[mt][nt2], ph[mt], vh0, vh1);
                    mma_bf16(o[mt][nt2], ph[mt], vl0, vl1);
                    mma_bf16(o[mt][nt2], pl[mt], vh0, vh1);
                }
            }
        }
    }

    #pragma unroll
    for (int q = 0; q < 4; q++){
        l[q] += __shfl_xor_sync(0xffffffffu, l[q], 1);
        l[q] += __shfl_xor_sync(0xffffffffu, l[q], 2);
        l[q] = 1.0f / l[q];
    }
    #pragma unroll
    for (int mt = 0; mt < 2; mt++){
        int r1 = wid*32 + mt*16 + gid, r2 = r1 + 8;
        float* o1 = out + (pixbase + (size_t)(r1>>4)*128 + (r1&15))*192 + h*32;
        float* o2 = out + (pixbase + (size_t)(r2>>4)*128 + (r2&15))*192 + h*32;
        #pragma unroll
        for (int nt2 = 0; nt2 < 4; nt2++){
            int dc = nt2*8 + 2*tig;
            float2 v1 = { o[mt][nt2][0]*l[2*mt],   o[mt][nt2][1]*l[2*mt] };
            float2 v2 = { o[mt][nt2][2]*l[2*mt+1], o[mt][nt2][3]*l[2*mt+1] };
            *(float2*)(o1 + dc) = v1;
            *(float2*)(o2 + dc) = v2;
        }
    }
}

// ---------------------------------------------------------------------------
extern "C" void kernel_launch(void* const* d_in, const int* in_sizes, int n_in,
                              void* d_out, int out_size)
{
    const float* x      = (const float*)d_in[0];
    const float* p1_w   = (const float*)d_in[1];
    const float* p1_b   = (const float*)d_in[2];
    const float* pw_w   = (const float*)d_in[3];
    const float* pw_b   = (const float*)d_in[4];
    const float* dw_w   = (const float*)d_in[5];
    const float* dw_b   = (const float*)d_in[6];
    const float* dd_w   = (const float*)d_in[7];
    const float* dd_b   = (const float*)d_in[8];
    const float* p2_w   = (const float*)d_in[9];
    const float* p2_b   = (const float*)d_in[10];
    const float* ln_g   = (const float*)d_in[11];
    const float* ln_b   = (const float*)d_in[12];
    const float* qkv_w  = (const float*)d_in[13];
    const float* q_bias = (const float*)d_in[14];
    const float* v_bias = (const float*)d_in[15];
    const float* lsc    = (const float*)d_in[16];
    const float* cpb_w1 = (const float*)d_in[17];
    const float* cpb_b1 = (const float*)d_in[18];
    const float* cpb_w2 = (const float*)d_in[19];
    const float* proj_w = (const float*)d_in[20];
    const float* proj_b = (const float*)d_in[21];
    float* outp = (float*)d_out;

    float *gy, *ga, *gb, *gq, *gt, *gbias, *gst;
    cudaGetSymbolAddress((void**)&gy, g_y);
    cudaGetSymbolAddress((void**)&ga, g_a);
    cudaGetSymbolAddress((void**)&gb, g_b);
    cudaGetSymbolAddress((void**)&gq, g_qkv);
    cudaGetSymbolAddress((void**)&gt, g_tbl);
    cudaGetSymbolAddress((void**)&gbias, g_bias);
    cudaGetSymbolAddress((void**)&gst, g_stats);

    const int ATTN_SMEM = (2*16*264 + 2*128*40 + 256) * 4;
    cudaFuncSetAttribute(k_attn, cudaFuncAttributeMaxDynamicSharedMemorySize, ATTN_SMEM);
    const int GEMM_SMEM_LOAD  = (64*20*2 + 16*264*2) * 4;        // 44032
    const int GEMM_SMEM_STAGE = 256*68*4;                        // 69632 ([pixel][68] overlay)
    cudaFuncSetAttribute(k_gemm<2>, cudaFuncAttributeMaxDynamicSharedMemorySize, GEMM_SMEM_STAGE);
    cudaFuncSetAttribute(k_gemm<3>, cudaFuncAttributeMaxDynamicSharedMemorySize, GEMM_SMEM_STAGE);

    dim3 gNCHW(HW/256, 3, BATCH);

    // zero LN partial sums (accumulated atomically by p2 epilogue)
    cudaMemsetAsync(gst, 0, (size_t)NPIX*2*sizeof(float));

    // CPB bias table + expansion (independent of main chain)
    k_cpb<<<961, 128>>>(cpb_w1, cpb_b1, cpb_w2, gt);
    k_bias<<<dim3(256, NH), 256>>>(gt, lsc, gbias);

    // VAB conv block
    k_gemm<0><<<gNCHW, 256, GEMM_SMEM_LOAD>>>(x,  p1_w, p1_b, nullptr, nullptr, nullptr, nullptr, gy, gst);
    k_gemm<1><<<gNCHW, 256, GEMM_SMEM_LOAD>>>(gy, pw_w, pw_b, nullptr, nullptr, nullptr, nullptr, ga, gst);
    k_dwf<<<dim3(16, BATCH*C), 256>>>(ga, dw_w, dw_b, dd_w, dd_b, gb);
    k_gemm<2><<<gNCHW, 256, GEMM_SMEM_STAGE>>>(gy, p2_w, p2_b, gb, x, nullptr, nullptr, ga, gst);

    // QKV projection with fused LayerNorm (stats accumulated by p2)
    k_gemm<3><<<dim3(NPIX/256, 9), 256, GEMM_SMEM_STAGE>>>(ga, qkv_w, ln_b, gst, ln_g, q_bias, v_bias, gq, gst);

    // Tensor-core windowed attention -> BHWC in gy
    k_attn<<<dim3(NWIN, NH), 256, ATTN_SMEM>>>(gq, gbias, lsc, gy);

    // Output projection -> NCHW d_out
    k_gemm<4><<<dim3(NPIX/256, 3), 256, GEMM_SMEM_LOAD>>>(gy, proj_w, proj_b, nullptr, nullptr, nullptr, nullptr, outp, gst);
}

// round 16
// speedup vs baseline: 1.2167x; 1.0722x over previous
#include <cuda_runtime.h>
#include <cuda_bf16.h>
#include <math.h>

#define BATCH 4
#define C 192
#define HW 16384            // 128*128
#define NPIX (BATCH*HW)     // 65536
#define NH 6
#define HD 32
#define NWIN 256
#define NTOK 256
#define LOG2E 1.44269504088896f

// ---------------- scratch (device globals; no allocations allowed) ----------
__device__ float g_y[BATCH*C*HW];
__device__ float g_a[BATCH*C*HW];
__device__ float g_b[BATCH*C*HW];
__device__ float g_qkv[(size_t)NPIX*576];
__device__ float g_tbl[961*NH];
__device__ float g_bias[NH*256*256];       // expanded CPB bias (log2-domain, pre-shifted)
__device__ float g_stats[NPIX*2];          // per-pixel LN partial (S, S2)

// ---------------- fast exp2 on the FMA pipe (input already log2-domain) -----
__device__ __forceinline__ float fexp2(float z){
    z = fmaxf(z, -126.0f);
    float mz = z + 12582912.0f;
    int   iz = __float_as_int(mz);
    float f  = z - (mz - 12582912.0f);
    float p  = 1.0f + f*(0.6931471806f + f*(0.2402265070f + f*(0.0555041087f
              + f*(0.0096181291f + f*0.0013333558f))));
    return __int_as_float(__float_as_int(p) + (iz << 23));
}

// ---------------- bf16 split helpers ---------------------------------------
__device__ __forceinline__ unsigned packbf(float lo, float hi){
    unsigned r;
    asm("cvt.rn.bf16x2.f32 %0, %1, %2;" : "=r"(r) : "f"(hi), "f"(lo));
    return r;
}
__device__ __forceinline__ float bflo(unsigned u){ return __uint_as_float(u << 16); }
__device__ __forceinline__ float bfhi(unsigned u){ return __uint_as_float(u & 0xffff0000u); }

__device__ __forceinline__ void split2(float a, float b, unsigned& h, unsigned& l){
    h = packbf(a, b);
    l = packbf(a - bflo(h), b - bfhi(h));
}

__device__ __forceinline__ void mma_bf16(float c[4], const unsigned a[4],
                                         unsigned b0, unsigned b1){
    asm("mma.sync.aligned.m16n8k16.row.col.f32.bf16.bf16.f32 "
        "{%0,%1,%2,%3},{%4,%5,%6,%7},{%8,%9},{%0,%1,%2,%3};"
        : "+f"(c[0]), "+f"(c[1]), "+f"(c[2]), "+f"(c[3])
        : "r"(a[0]), "r"(a[1]), "r"(a[2]), "r"(a[3]), "r"(b0), "r"(b1));
}

// ---------------- CPB MLP table --------------------------------------------
__global__ void k_cpb(const float* __restrict__ w1, const float* __restrict__ b1,
                      const float* __restrict__ w2, float* __restrict__ tbl)
{
    int r = blockIdx.x;
    int t = threadIdx.x;
    float dy = (float)(r / 31) - 15.0f;
    float dx = (float)(r % 31) - 15.0f;
    float u0 = dy / 15.0f * 8.0f, u1 = dx / 15.0f * 8.0f;
    float t0 = copysignf(log2f(fabsf(u0) + 1.0f) * (1.0f/3.0f), u0);
    float t1 = copysignf(log2f(fabsf(u1) + 1.0f) * (1.0f/3.0f), u1);
    float acc[6] = {0,0,0,0,0,0};
    for (int u = t; u < 512; u += 128){
        float hv = fmaxf(w1[2*u]*t0 + w1[2*u+1]*t1 + b1[u], 0.0f);
        #pragma unroll
        for (int h = 0; h < 6; h++) acc[h] += hv * w2[h*512 + u];
    }
    __shared__ float red[6][128];
    #pragma unroll
    for (int h = 0; h < 6; h++) red[h][t] = acc[h];
    __syncthreads();
    for (int off = 64; off > 0; off >>= 1){
        if (t < off){
            #pragma unroll
            for (int h = 0; h < 6; h++) red[h][t] += red[h][t+off];
        }
        __syncthreads();
    }
    if (t < 6){
        float v = red[t][0];
        tbl[r*6 + t] = 16.0f / (1.0f + expf(-v));
    }
}

// ---------------- expand CPB bias to [h][256][256], log2 domain, -m_h -------
__global__ void k_bias(const float* __restrict__ tbl, const float* __restrict__ lsc,
                       float* __restrict__ bg)
{
    int r = blockIdx.x, h = blockIdx.y, c = threadIdx.x;
    int iy = r >> 4, ix = r & 15, my = c >> 4, mx = c & 15;
    int idx = (iy - my + 15)*31 + (ix - mx + 15);
    float scale = __expf(fminf(lsc[h], 4.6051702f));
    bg[((size_t)h*256 + r)*256 + c] = (tbl[idx*6 + h] - (scale + 16.0f)) * LOG2E;
}

// ---------------- tensor-core GEMM (bf16 hi/lo split, fp32 accum) ----------
// MODE 0: p1; 1: pw; 2: p2 (gate+res->BHWC, accumulates LN stats);
// MODE 3: qkv (inline LN from raw sums); 4: proj->NCHW
// B smem stride 264 -> conflict-free fragment loads. Epilogue stage (modes
// 2,3) is [pixel][68] -> conflict-free stores, vectorized reads.
template<int MODE>
__global__ void __launch_bounds__(256, 2)
k_gemm(const float* __restrict__ X, const float* __restrict__ W,
       const float* __restrict__ bias, const float* __restrict__ X2,
       const float* __restrict__ res, const float* __restrict__ qb,
       const float* __restrict__ vb, float* __restrict__ out,
       float* __restrict__ stats)
{
    // MODE 3 reinterprets: bias = ln_b, res = ln_g, X2 = raw stats (S, S2)
    extern __shared__ unsigned smem_u[];
    unsigned* Ah = smem_u;                  // 64*20
    unsigned* Al = Ah + 64*20;
    unsigned* Bh = Al + 64*20;              // 16*264
    unsigned* Bl = Bh + 16*264;
    float* sstat = (float*)(Bl + 16*264);   // mode 3: [256]*(mu,rs) @ 44032 B
    float* stg = (float*)smem_u;            // overlay (modes 2,3 epilogue): [256][68]

    const int t = threadIdx.x;
    const int wid = t >> 5, lane = t & 31;
    const int gid = lane >> 2, tig = lane & 3;
    const int m0w = (wid & 1) * 32;
    const int n0w = (wid >> 1) * 64;

    const int p0  = blockIdx.x * 256;
    const int co0 = blockIdx.y * 64;
    const int bz  = (MODE <= 2) ? blockIdx.z : 0;

    const float* Xb  = (MODE <= 2) ? (X + (size_t)bz*C*HW) : X;
    const float* X2b = (MODE == 2) ? (X2 + (size_t)bz*C*HW) : nullptr;

    float c[2][8][4];
    #pragma unroll
    for (int i = 0; i < 2; i++)
        #pragma unroll
        for (int j = 0; j < 8; j++)
            #pragma unroll
            for (int q = 0; q < 4; q++) c[i][j][q] = 0.0f;

    const int ar  = t >> 2;
    const int akq = (t & 3) * 8;

    if (MODE == 3){
        // per-pixel LN stats from raw sums
        float2 ssum = *(const float2*)&X2[(size_t)(p0 + t)*2];
        float mu = ssum.x * (1.0f/192.0f);
        float var = ssum.y * (1.0f/192.0f) - mu*mu;
        float rs = rsqrtf(var + 1e-5f);
        sstat[2*t] = mu; sstat[2*t+1] = rs;
    }

    for (int kc = 0; kc < 6; kc++){
        const int k0 = kc * 32;
        __syncthreads();
        {
            const float* wp = &W[(size_t)(co0 + ar)*192 + k0 + akq];
            float4 w0 = *(const float4*)wp;
            float4 w1 = *(const float4*)(wp + 4);
            uint4 h, l;
            split2(w0.x, w0.y, h.x, l.x);
            split2(w0.z, w0.w, h.y, l.y);
            split2(w1.x, w1.y, h.z, l.z);
            split2(w1.z, w1.w, h.w, l.w);
            *(uint4*)&Ah[ar*20 + akq/2] = h;
            *(uint4*)&Al[ar*20 + akq/2] = l;
        }
        if (MODE <= 2){
            const int bp  = (t & 63) * 4;
            const int bk2 = t >> 6;
            #pragma unroll
            for (int r = 0; r < 4; r++){
                int k2i = bk2 + r*4;
                int k = k0 + k2i*2;
                const float* xr = Xb + (size_t)k*HW + p0 + bp;
                float4 e = *(const float4*)xr;
                float4 o = *(const float4*)(xr + HW);
                if (MODE == 2){
                    const float* mr = X2b + (size_t)k*HW + p0 + bp;
                    float4 m1 = *(const float4*)mr;
                    float4 m2 = *(const float4*)(mr + HW);
                    e.x*=m1.x; e.y*=m1.y; e.z*=m1.z; e.w*=m1.w;
                    o.x*=m2.x; o.y*=m2.y; o.z*=m2.z; o.w*=m2.w;
                }
                uint4 h, l;
                split2(e.x, o.x, h.x, l.x);
                split2(e.y, o.y, h.y, l.y);
                split2(e.z, o.z, h.z, l.z);
                split2(e.w, o.w, h.w, l.w);
                *(uint4*)&Bh[k2i*264 + bp] = h;
                *(uint4*)&Bl[k2i*264 + bp] = l;
            }
        } else {
            const int fi = t & 7;
            const int k = k0 + fi*4;
            float4 gv, bv4;
            if (MODE == 3){
                gv  = *(const float4*)&res[k];     // ln gamma
                bv4 = *(const float4*)&bias[k];    // ln beta
            }
            #pragma unroll
            for (int r = 0; r < 8; r++){
                int pl = (t >> 3) + r*32;
                float4 v = *(const float4*)&Xb[(size_t)(p0 + pl)*192 + k];
                if (MODE == 3){
                    float2 st = *(const float2*)&sstat[2*pl];
                    v.x = (v.x - st.x)*st.y*gv.x + bv4.x;
                    v.y = (v.y - st.x)*st.y*gv.y + bv4.y;
                    v.z = (v.z - st.x)*st.y*gv.z + bv4.z;
                    v.w = (v.w - st.x)*st.y*gv.w + bv4.w;
                }
                unsigned h0, l0, h1, l1;
                split2(v.x, v.y, h0, l0);
                split2(v.z, v.w, h1, l1);
                Bh[(fi*2  )*264 + pl] = h0;
                Bh[(fi*2+1)*264 + pl] = h1;
                Bl[(fi*2  )*264 + pl] = l0;
                Bl[(fi*2+1)*264 + pl] = l1;
            }
        }
        __syncthreads();

        #pragma unroll
        for (int ks = 0; ks < 2; ks++){
            const int kb = ks * 8;
            unsigned ah[2][4], al2[2][4];
            #pragma unroll
            for (int mt = 0; mt < 2; mt++){
                int mr = m0w + mt*16 + gid;
                ah[mt][0]  = Ah[mr*20 + kb + tig];
                ah[mt][1]  = Ah[(mr+8)*20 + kb + tig];
                ah[mt][2]  = Ah[mr*20 + kb + tig + 4];
                ah[mt][3]  = Ah[(mr+8)*20 + kb + tig + 4];
                al2[mt][0] = Al[mr*20 + kb + tig];
                al2[mt][1] = Al[(mr+8)*20 + kb + tig];
                al2[mt][2] = Al[mr*20 + kb + tig + 4];
                al2[mt][3] = Al[(mr+8)*20 + kb + tig + 4];
            }
            #pragma unroll
            for (int nt = 0; nt < 8; nt++){
                int nn = n0w + nt*8 + gid;
                unsigned bh0 = Bh[(kb+tig  )*264 + nn];
                unsigned bh1 = Bh[(kb+tig+4)*264 + nn];
                unsigned bl0 = Bl[(kb+tig  )*264 + nn];
                unsigned bl1 = Bl[(kb+tig+4)*264 + nn];
                #pragma unroll
                for (int mt = 0; mt < 2; mt++){
                    mma_bf16(c[mt][nt], ah[mt],  bh0, bh1);
                    mma_bf16(c[mt][nt], ah[mt],  bl0, bl1);
                    mma_bf16(c[mt][nt], al2[mt], bh0, bh1);
                }
            }
        }
    }

    if (MODE == 0 || MODE == 1){
        #pragma unroll
        for (int mt = 0; mt < 2; mt++){
            #pragma unroll
            for (int s = 0; s < 2; s++){
                int rl = m0w + mt*16 + gid + s*8;
                float bv = bias[co0 + rl];
                float* orow = out + ((size_t)bz*C + co0 + rl)*HW + p0;
                #pragma unroll
                for (int nt = 0; nt < 8; nt++){
                    int cs = n0w + nt*8 + tig*2;
                    float v0 = c[mt][nt][s*2+0] + bv;
                    float v1 = c[mt][nt][s*2+1] + bv;
                    if (MODE == 0){
                        v0 = 0.5f*v0*(1.0f + erff(v0*0.70710678f));
                        v1 = 0.5f*v1*(1.0f + erff(v1*0.70710678f));
                    }
                    float2 v = {v0, v1};
                    *(float2*)&orow[cs] = v;
                }
            }
        }
    } else if (MODE == 4){
        const int bb = p0 >> 14;
        const int hw0 = p0 & 16383;
        #pragma unroll
        for (int mt = 0; mt < 2; mt++){
            #pragma unroll
            for (int s = 0; s < 2; s++){
                int rl = m0w + mt*16 + gid + s*8;
                float bv = bias[co0 + rl];
                float* orow = out + ((size_t)bb*C + co0 + rl)*HW + hw0;
                #pragma unroll
                for (int nt = 0; nt < 8; nt++){
                    int cs = n0w + nt*8 + tig*2;
                    float2 v = {c[mt][nt][s*2+0] + bv, c[mt][nt][s*2+1] + bv};
                    *(float2*)&orow[cs] = v;
                }
            }
        }
    } else {
        // modes 2,3: stage transposed [pixel][68] -> conflict-free STS,
        // vectorized LDS.128 reads
        __syncthreads();
        #pragma unroll
        for (int mt = 0; mt < 2; mt++){
            #pragma unroll
            for (int s = 0; s < 2; s++){
                int rl = m0w + mt*16 + gid + s*8;
                float bv;
                if (MODE == 3){
                    int co = co0 + rl;
                    bv = (co < 192) ? qb[co] : (co < 384 ? 0.0f : vb[co - 384]);
                } else {
                    bv = bias[co0 + rl];
                }
                const float* rrow = (MODE == 2)
                    ? (res + ((size_t)bz*C + co0 + rl)*HW + p0) : nullptr;
                #pragma unroll
                for (int nt = 0; nt < 8; nt++){
                    int cs = n0w + nt*8 + tig*2;
                    float v0 = c[mt][nt][s*2+0] + bv;
                    float v1 = c[mt][nt][s*2+1] + bv;
                    if (MODE == 2){
                        float2 rv = *(const float2*)&rrow[cs];
                        v0 += rv.x; v1 += rv.y;
                    }
                    stg[(size_t)cs*68 + rl]       = v0;
                    stg[(size_t)(cs+1)*68 + rl]   = v1;
                }
            }
        }
        __syncthreads();
        const int ldo = (MODE == 3) ? 576 : 192;
        const size_t pbase = (MODE == 3) ? (size_t)p0 : ((size_t)bz*HW + p0);
        #pragma unroll
        for (int r = 0; r < 4; r++){
            int pl = (t >> 2) + r*64;
            int cq = (t & 3) * 16;
            float vals[16];
            const float* rowp = &stg[(size_t)pl*68 + cq];
            *(float4*)&vals[0]  = *(const float4*)&rowp[0];
            *(float4*)&vals[4]  = *(const float4*)&rowp[4];
            *(float4*)&vals[8]  = *(const float4*)&rowp[8];
            *(float4*)&vals[12] = *(const float4*)&rowp[12];
            if (MODE == 2){
                float s = 0.0f, s2 = 0.0f;
                #pragma unroll
                for (int j = 0; j < 16; j++){ s += vals[j]; s2 += vals[j]*vals[j]; }
                s  += __shfl_xor_sync(0xffffffffu, s, 1);
                s  += __shfl_xor_sync(0xffffffffu, s, 2);
                s2 += __shfl_xor_sync(0xffffffffu, s2, 1);
                s2 += __shfl_xor_sync(0xffffffffu, s2, 2);
                if ((t & 3) == 0){
                    size_t px = (size_t)bz*HW + p0 + pl;
                    atomicAdd(&stats[px*2],     s);
                    atomicAdd(&stats[px*2 + 1], s2);
                }
            }
            float* op = out + (pbase + pl)*ldo + co0 + cq;
            *(float4*)&op[0]  = *(float4*)&vals[0];
            *(float4*)&op[4]  = *(float4*)&vals[4];
            *(float4*)&op[8]  = *(float4*)&vals[8];
            *(float4*)&op[12] = *(float4*)&vals[12];
        }
    }
}

// ---------------- fused depthwise 5x5 + 5x5 dil3 (64x64 tile, 2-row conv1) --
// dynamic smem: wts[52] | s0[80][84] | s1[76][84]
__global__ void __launch_bounds__(256)
k_dwf(const float* __restrict__ in, const float* __restrict__ w1,
      const float* __restrict__ b1, const float* __restrict__ w2,
      const float* __restrict__ b2, float* __restrict__ out)
{
    extern __shared__ float dsm[];
    float* wts = dsm;                 // 52
    float* s0  = dsm + 52;            // 80*84
    float* s1  = s0 + 80*84;          // 76*84

    const int plane = blockIdx.y;     // b*C + c
    const int c = plane % C;
    const int tile = blockIdx.x;      // 0..3
    const int y0 = (tile >> 1) * 64, x0 = (tile & 1) * 64;
    const int t = threadIdx.x;

    if (t < 25) wts[t] = w1[c*25 + t];
    else if (t < 50) wts[t] = w2[c*25 + t - 25];
    else if (t == 50) wts[50] = b1[c];
    else if (t == 51) wts[51] = b2[c];

    const float* ip = in + ((size_t)plane << 14);
    for (int idx = t; idx < 80*84; idx += 256){
        int yy = idx / 84, xx = idx - yy*84;
        int gy = y0 - 8 + yy, gx = x0 - 8 + xx;
        s0[yy*84 + xx] = ((unsigned)gy < 128u && (unsigned)gx < 128u) ? ip[gy*128+gx] : 0.0f;
    }
    __syncthreads();

    // conv1 (dense 5x5): 380 units, each 2 rows x 8 cols from 6 input rows
    for (int u = t; u < 380; u += 256){
        int rp = u / 10, cg = u - 10*rp;
        int r = rp * 2;                  // s1 rows r, r+1 (r <= 74)
        int c0 = cg * 8;                 // s1 cols c0..c0+7
        float a0[8], a1[8];
        #pragma unroll
        for (int cc = 0; cc < 8; cc++){ a0[cc] = wts[50]; a1[cc] = wts[50]; }
        #pragma unroll
        for (int i2 = 0; i2 < 6; i2++){
            float row[12];
            const float* sp = &s0[(r+i2)*84 + c0];
            *(float4*)&row[0] = *(const float4*)&sp[0];
            *(float4*)&row[4] = *(const float4*)&sp[4];
            *(float4*)&row[8] = *(const float4*)&sp[8];
            if (i2 < 5){
                #pragma unroll
                for (int j = 0; j < 5; j++){
                    float wv = wts[i2*5+j];
                    #pragma unroll
                    for (int cc = 0; cc < 8; cc++)
                        a0[cc] = fmaf(wv, row[cc+j], a0[cc]);
                }
            }
            if (i2 > 0){
                #pragma unroll
                for (int j = 0; j < 5; j++){
                    float wv = wts[(i2-1)*5+j];
                    #pragma unroll
                    for (int cc = 0; cc < 8; cc++)
                        a1[cc] = fmaf(wv, row[cc+j], a1[cc]);
                }
            }
        }
        int gy0 = y0 - 6 + r;
        bool ok0 = (unsigned)gy0 < 128u;
        bool ok1 = (unsigned)(gy0+1) < 128u;
        #pragma unroll
        for (int cc = 0; cc < 8; cc++){
            int gx = x0 - 6 + c0 + cc;
            bool cok = (unsigned)gx < 128u;
            s1[r*84 + c0 + cc]     = (ok0 && cok) ? a0[cc] : 0.0f;
            s1[(r+1)*84 + c0 + cc] = (ok1 && cok) ? a1[cc] : 0.0f;
        }
    }
    __syncthreads();

    // conv2 (5x5 dil 3): 1024 units, each 1 row x 4 cols
    for (int u = t; u < 1024; u += 256){
        int row = u >> 4, cg = u & 15;
        int c0 = cg * 4;
        float acc[4];
        #pragma unroll
        for (int cc = 0; cc < 4; cc++) acc[cc] = wts[51];
        #pragma unroll
        for (int i = 0; i < 5; i++){
            float rw[16];
            const float* sp = &s1[(row+3*i)*84 + c0];
            *(float4*)&rw[0]  = *(const float4*)&sp[0];
            *(float4*)&rw[4]  = *(const float4*)&sp[4];
            *(float4*)&rw[8]  = *(const float4*)&sp[8];
            *(float4*)&rw[12] = *(const float4*)&sp[12];
            #pragma unroll
            for (int j = 0; j < 5; j++){
                float wv = wts[25+i*5+j];
                #pragma unroll
                for (int cc = 0; cc < 4; cc++)
                    acc[cc] = fmaf(wv, rw[3*j+cc], acc[cc]);
            }
        }
        *(float4*)&out[((size_t)plane << 14) + (y0+row)*128 + x0 + c0] = *(float4*)&acc[0];
    }
}

// ---------------- SwinV2 cosine window attention (tensor-core flash) --------
// fixed-shift softmax in log2 domain; 32-col half-chunks, 2 CTAs/SM
__global__ void __launch_bounds__(256, 2)
k_attn(const float* __restrict__ qkv, const float* __restrict__ bgl,
       const float* __restrict__ lsc, float* __restrict__ out)
{
    extern __shared__ unsigned sm[];
    unsigned* Kh = sm;                     // [16][264]
    unsigned* Kl = Kh + 16*264;
    unsigned* Vh = Kl + 16*264;            // [128][40]
    unsigned* Vl = Vh + 128*40;
    float* qs = (float*)(Vl + 128*40);     // [256]

    const int w = blockIdx.x, h = blockIdx.y, t = threadIdx.x;
    const int b = w >> 6, wy = (w >> 3) & 7, wx = w & 7;
    const int wid = t >> 5, lane = t & 31, gid = lane >> 2, tig = lane & 3;
    const float scale = __expf(fminf(lsc[h], 4.6051702f));
    const size_t pixbase = (size_t)b*HW + (size_t)(wy*16)*128 + wx*16;

    {
        const int tok = t;
        const size_t pp = pixbase + (size_t)(tok >> 4)*128 + (tok & 15);
        const float* qr = qkv + pp*576 + h*32;
        const float* kr = qr + 192;
        float kv[32]; float ssq = 0.0f, ssk = 0.0f;
        #pragma unroll
        for (int d = 0; d < 8; d++){
            float4 q4 = ((const float4*)qr)[d];
            ssq += q4.x*q4.x + q4.y*q4.y + q4.z*q4.z + q4.w*q4.w;
            float4 k4 = ((const float4*)kr)[d];
            kv[4*d]=k4.x; kv[4*d+1]=k4.y; kv[4*d+2]=k4.z; kv[4*d+3]=k4.w;
            ssk += k4.x*k4.x + k4.y*k4.y + k4.z*k4.z + k4.w*k4.w;
        }
        qs[tok] = scale * LOG2E / fmaxf(sqrtf(ssq), 1e-12f);
        float ki = 1.0f / fmaxf(sqrtf(ssk), 1e-12f);
        #pragma unroll
        for (int d2 = 0; d2 < 16; d2++){
            unsigned hh, ll;
            split2(kv[2*d2]*ki, kv[2*d2+1]*ki, hh, ll);
            Kh[d2*264 + tok] = hh;
            Kl[d2*264 + tok] = ll;
        }
    }
    {
        const int t2 = t >> 1, dh = (t & 1) * 16;
        const size_t pa = pixbase + (size_t)((2*t2) >> 4)*128 + ((2*t2) & 15);
        const size_t pb = pixbase + (size_t)((2*t2+1) >> 4)*128 + ((2*t2+1) & 15);
        const float* v0 = qkv + pa*576 + 384 + h*32 + dh;
        const float* v1 = qkv + pb*576 + 384 + h*32 + dh;
        #pragma unroll
        for (int dq = 0; dq < 4; dq++){
            float4 a = ((const float4*)v0)[dq];
            float4 bb = ((const float4*)v1)[dq];
            unsigned hh, ll;
            split2(a.x, bb.x, hh, ll); Vh[t2*40+dh+4*dq+0]=hh; Vl[t2*40+dh+4*dq+0]=ll;
            split2(a.y, bb.y, hh, ll); Vh[t2*40+dh+4*dq+1]=hh; Vl[t2*40+dh+4*dq+1]=ll;
            split2(a.z, bb.z, hh, ll); Vh[t2*40+dh+4*dq+2]=hh; Vl[t2*40+dh+4*dq+2]=ll;
            split2(a.w, bb.w, hh, ll); Vh[t2*40+dh+4*dq+3]=hh; Vl[t2*40+dh+4*dq+3]=ll;
        }
    }
    __syncthreads();

    unsigned qh[2][2][4], ql[2][2][4];
    #pragma unroll
    for (int mt = 0; mt < 2; mt++){
        int r1 = wid*32 + mt*16 + gid, r2 = r1 + 8;
        float s1 = qs[r1], s2 = qs[r2];
        const float* q1 = qkv + (pixbase + (size_t)(r1>>4)*128 + (r1&15))*576 + h*32;
        const float* q2 = qkv + (pixbase + (size_t)(r2>>4)*128 + (r2&15))*576 + h*32;
        #pragma unroll
        for (int ks = 0; ks < 2; ks++){
            float2 e1 = *(const float2*)(q1 + 16*ks + 2*tig);
            float2 e2 = *(const float2*)(q2 + 16*ks + 2*tig);
            float2 f1 = *(const float2*)(q1 + 16*ks + 8 + 2*tig);
            float2 f2 = *(const float2*)(q2 + 16*ks + 8 + 2*tig);
            split2(e1.x*s1, e1.y*s1, qh[mt][ks][0], ql[mt][ks][0]);
            split2(e2.x*s2, e2.y*s2, qh[mt][ks][1], ql[mt][ks][1]);
            split2(f1.x*s1, f1.y*s1, qh[mt][ks][2], ql[mt][ks][2]);
            split2(f2.x*s2, f2.y*s2, qh[mt][ks][3], ql[mt][ks][3]);
        }
    }

    float l[4] = {0,0,0,0};
    float o[2][4][4];
    #pragma unroll
    for (int i=0;i<2;i++) for (int j=0;j<4;j++) for (int q=0;q<4;q++) o[i][j][q]=0.0f;

    const float* bg = bgl + (size_t)h*256*256;

    for (int ch = 0; ch < 8; ch++){
        const int c0 = ch * 32;
        float c[2][4][4];
        #pragma unroll
        for (int i=0;i<2;i++) for (int j=0;j<4;j++) for (int q=0;q<4;q++) c[i][j][q]=0.0f;

        #pragma unroll
        for (int ks = 0; ks < 2; ks++){
            #pragma unroll
            for (int nt = 0; nt < 4; nt++){
                int n = c0 + nt*8 + gid;
                unsigned bh0 = Kh[(8*ks+tig  )*264 + n];
                unsigned bh1 = Kh[(8*ks+tig+4)*264 + n];
                unsigned bl0 = Kl[(8*ks+tig  )*264 + n];
                unsigned bl1 = Kl[(8*ks+tig+4)*264 + n];
                #pragma unroll
                for (int mt = 0; mt < 2; mt++){
                    mma_bf16(c[mt][nt], qh[mt][ks], bh0, bh1);
                    mma_bf16(c[mt][nt], qh[mt][ks], bl0, bl1);
                    mma_bf16(c[mt][nt], ql[mt][ks], bh0, bh1);
                }
            }
        }

        #pragma unroll
        for (int tt = 0; tt < 2; tt++){
            unsigned ph[2][4], pl[2][4];
            #pragma unroll
            for (int mt = 0; mt < 2; mt++){
                int r1 = wid*32 + mt*16 + gid, r2 = r1 + 8;
                int cc0 = c0 + (2*tt)*8 + 2*tig;
                int cc1 = c0 + (2*tt+1)*8 + 2*tig;
                float2 ba = *(const float2*)&bg[(size_t)r1*256 + cc0];
                float2 bb2 = *(const float2*)&bg[(size_t)r2*256 + cc0];
                float2 bc = *(const float2*)&bg[(size_t)r1*256 + cc1];
                float2 bd = *(const float2*)&bg[(size_t)r2*256 + cc1];
                float p0 = fexp2(c[mt][2*tt  ][0] + ba.x);
                float p1 = fexp2(c[mt][2*tt  ][1] + ba.y);
                float p2 = fexp2(c[mt][2*tt  ][2] + bb2.x);
                float p3 = fexp2(c[mt][2*tt  ][3] + bb2.y);
                float p4 = fexp2(c[mt][2*tt+1][0] + bc.x);
                float p5 = fexp2(c[mt][2*tt+1][1] + bc.y);
                float p6 = fexp2(c[mt][2*tt+1][2] + bd.x);
                float p7 = fexp2(c[mt][2*tt+1][3] + bd.y);
                l[2*mt]   += p0 + p1 + p4 + p5;
                l[2*mt+1] += p2 + p3 + p6 + p7;
                split2(p0, p1, ph[mt][0], pl[mt][0]);
                split2(p2, p3, ph[mt][1], pl[mt][1]);
                split2(p4, p5, ph[mt][2], pl[mt][2]);
                split2(p6, p7, ph[mt][3], pl[mt][3]);
            }
            const int base = (c0 + 16*tt) >> 1;
            #pragma unroll
            for (int nt2 = 0; nt2 < 4; nt2++){
                int dcol = nt2*8 + gid;
                unsigned vh0 = Vh[(base+tig  )*40 + dcol];
                unsigned vh1 = Vh[(base+tig+4)*40 + dcol];
                unsigned vl0 = Vl[(base+tig  )*40 + dcol];
                unsigned vl1 = Vl[(base+tig+4)*40 + dcol];
                #pragma unroll
                for (int mt = 0; mt < 2; mt++){
                    mma_bf16(o[mt][nt2], ph[mt], vh0, vh1);
                    mma_bf16(o[mt][nt2], ph[mt], vl0, vl1);
                    mma_bf16(o[mt][nt2], pl[mt], vh0, vh1);
                }
            }
        }
    }

    #pragma unroll
    for (int q = 0; q < 4; q++){
        l[q] += __shfl_xor_sync(0xffffffffu, l[q], 1);
        l[q] += __shfl_xor_sync(0xffffffffu, l[q], 2);
        l[q] = 1.0f / l[q];
    }
    #pragma unroll
    for (int mt = 0; mt < 2; mt++){
        int r1 = wid*32 + mt*16 + gid, r2 = r1 + 8;
        float* o1 = out + (pixbase + (size_t)(r1>>4)*128 + (r1&15))*192 + h*32;
        float* o2 = out + (pixbase + (size_t)(r2>>4)*128 + (r2&15))*192 + h*32;
        #pragma unroll
        for (int nt2 = 0; nt2 < 4; nt2++){
            int dc = nt2*8 + 2*tig;
            float2 v1 = { o[mt][nt2][0]*l[2*mt],   o[mt][nt2][1]*l[2*mt] };
            float2 v2 = { o[mt][nt2][2]*l[2*mt+1], o[mt][nt2][3]*l[2*mt+1] };
            *(float2*)(o1 + dc) = v1;
            *(float2*)(o2 + dc) = v2;
        }
    }
}

// ---------------------------------------------------------------------------
extern "C" void kernel_launch(void* const* d_in, const int* in_sizes, int n_in,
                              void* d_out, int out_size)
{
    const float* x      = (const float*)d_in[0];
    const float* p1_w   = (const float*)d_in[1];
    const float* p1_b   = (const float*)d_in[2];
    const float* pw_w   = (const float*)d_in[3];
    const float* pw_b   = (const float*)d_in[4];
    const float* dw_w   = (const float*)d_in[5];
    const float* dw_b   = (const float*)d_in[6];
    const float* dd_w   = (const float*)d_in[7];
    const float* dd_b   = (const float*)d_in[8];
    const float* p2_w   = (const float*)d_in[9];
    const float* p2_b   = (const float*)d_in[10];
    const float* ln_g   = (const float*)d_in[11];
    const float* ln_b   = (const float*)d_in[12];
    const float* qkv_w  = (const float*)d_in[13];
    const float* q_bias = (const float*)d_in[14];
    const float* v_bias = (const float*)d_in[15];
    const float* lsc    = (const float*)d_in[16];
    const float* cpb_w1 = (const float*)d_in[17];
    const float* cpb_b1 = (const float*)d_in[18];
    const float* cpb_w2 = (const float*)d_in[19];
    const float* proj_w = (const float*)d_in[20];
    const float* proj_b = (const float*)d_in[21];
    float* outp = (float*)d_out;

    float *gy, *ga, *gb, *gq, *gt, *gbias, *gst;
    cudaGetSymbolAddress((void**)&gy, g_y);
    cudaGetSymbolAddress((void**)&ga, g_a);
    cudaGetSymbolAddress((void**)&gb, g_b);
    cudaGetSymbolAddress((void**)&gq, g_qkv);
    cudaGetSymbolAddress((void**)&gt, g_tbl);
    cudaGetSymbolAddress((void**)&gbias, g_bias);
    cudaGetSymbolAddress((void**)&gst, g_stats);

    const int ATTN_SMEM = (2*16*264 + 2*128*40 + 256) * 4;
    cudaFuncSetAttribute(k_attn, cudaFuncAttributeMaxDynamicSharedMemorySize, ATTN_SMEM);
    const int GEMM_SMEM_LOAD  = (64*20*2 + 16*264*2) * 4;        // 44032
    const int GEMM_SMEM_STAGE = 256*68*4;                        // 69632 ([pixel][68] overlay)
    cudaFuncSetAttribute(k_gemm<2>, cudaFuncAttributeMaxDynamicSharedMemorySize, GEMM_SMEM_STAGE);
    cudaFuncSetAttribute(k_gemm<3>, cudaFuncAttributeMaxDynamicSharedMemorySize, GEMM_SMEM_STAGE);
    const int DWF_SMEM = (52 + 80*84 + 76*84) * 4;               // 52624
    cudaFuncSetAttribute(k_dwf, cudaFuncAttributeMaxDynamicSharedMemorySize, DWF_SMEM);

    dim3 gNCHW(HW/256, 3, BATCH);

    // zero LN partial sums (accumulated atomically by p2 epilogue)
    cudaMemsetAsync(gst, 0, (size_t)NPIX*2*sizeof(float));

    // CPB bias table + expansion (independent of main chain)
    k_cpb<<<961, 128>>>(cpb_w1, cpb_b1, cpb_w2, gt);
    k_bias<<<dim3(256, NH), 256>>>(gt, lsc, gbias);

    // VAB conv block
    k_gemm<0><<<gNCHW, 256, GEMM_SMEM_LOAD>>>(x,  p1_w, p1_b, nullptr, nullptr, nullptr, nullptr, gy, gst);
    k_gemm<1><<<gNCHW, 256, GEMM_SMEM_LOAD>>>(gy, pw_w, pw_b, nullptr, nullptr, nullptr, nullptr, ga, gst);
    k_dwf<<<dim3(4, BATCH*C), 256, DWF_SMEM>>>(ga, dw_w, dw_b, dd_w, dd_b, gb);
    k_gemm<2><<<gNCHW, 256, GEMM_SMEM_STAGE>>>(gy, p2_w, p2_b, gb, x, nullptr, nullptr, ga, gst);

    // QKV projection with fused LayerNorm (stats accumulated by p2)
    k_gemm<3><<<dim3(NPIX/256, 9), 256, GEMM_SMEM_STAGE>>>(ga, qkv_w, ln_b, gst, ln_g, q_bias, v_bias, gq, gst);

    // Tensor-core windowed attention -> BHWC in gy
    k_attn<<<dim3(NWIN, NH), 256, ATTN_SMEM>>>(gq, gbias, lsc, gy);

    // Output projection -> NCHW d_out
    k_gemm<4><<<dim3(NPIX/256, 3), 256, GEMM_SMEM_LOAD>>>(gy, proj_w, proj_b, nullptr, nullptr, nullptr, nullptr, outp, gst);
}

// round 17
// speedup vs baseline: 1.2212x; 1.0037x over previous
#include <cuda_runtime.h>
#include <cuda_bf16.h>
#include <math.h>

#define BATCH 4
#define C 192
#define HW 16384            // 128*128
#define NPIX (BATCH*HW)     // 65536
#define NH 6
#define HD 32
#define NWIN 256
#define NTOK 256
#define LOG2E 1.44269504088896f

// PDL wait: block until all grid dependencies (previous kernel) complete.
__device__ __forceinline__ void pdl_wait(){
    asm volatile("griddepcontrol.wait;" ::: "memory");
}

// ---------------- scratch (device globals; no allocations allowed) ----------
__device__ float g_y[BATCH*C*HW];
__device__ float g_a[BATCH*C*HW];
__device__ float g_b[BATCH*C*HW];
__device__ float g_qkv[(size_t)NPIX*576];
__device__ float g_tbl[961*NH];
__device__ float g_bias[NH*256*256];       // expanded CPB bias (log2-domain, pre-shifted)
__device__ float g_stats[NPIX*2];          // per-pixel LN partial (S, S2)

// ---------------- fast exp2 on the FMA pipe (input already log2-domain) -----
__device__ __forceinline__ float fexp2(float z){
    z = fmaxf(z, -126.0f);
    float mz = z + 12582912.0f;
    int   iz = __float_as_int(mz);
    float f  = z - (mz - 12582912.0f);
    float p  = 1.0f + f*(0.6931471806f + f*(0.2402265070f + f*(0.0555041087f
              + f*(0.0096181291f + f*0.0013333558f))));
    return __int_as_float(__float_as_int(p) + (iz << 23));
}

// ---------------- bf16 split helpers ---------------------------------------
__device__ __forceinline__ unsigned packbf(float lo, float hi){
    unsigned r;
    asm("cvt.rn.bf16x2.f32 %0, %1, %2;" : "=r"(r) : "f"(hi), "f"(lo));
    return r;
}
__device__ __forceinline__ float bflo(unsigned u){ return __uint_as_float(u << 16); }
__device__ __forceinline__ float bfhi(unsigned u){ return __uint_as_float(u & 0xffff0000u); }

__device__ __forceinline__ void split2(float a, float b, unsigned& h, unsigned& l){
    h = packbf(a, b);
    l = packbf(a - bflo(h), b - bfhi(h));
}

__device__ __forceinline__ void mma_bf16(float c[4], const unsigned a[4],
                                         unsigned b0, unsigned b1){
    asm("mma.sync.aligned.m16n8k16.row.col.f32.bf16.bf16.f32 "
        "{%0,%1,%2,%3},{%4,%5,%6,%7},{%8,%9},{%0,%1,%2,%3};"
        : "+f"(c[0]), "+f"(c[1]), "+f"(c[2]), "+f"(c[3])
        : "r"(a[0]), "r"(a[1]), "r"(a[2]), "r"(a[3]), "r"(b0), "r"(b1));
}

// ---------------- CPB MLP table --------------------------------------------
__global__ void k_cpb(const float* __restrict__ w1, const float* __restrict__ b1,
                      const float* __restrict__ w2, float* __restrict__ tbl)
{
    int r = blockIdx.x;
    int t = threadIdx.x;
    float dy = (float)(r / 31) - 15.0f;
    float dx = (float)(r % 31) - 15.0f;
    float u0 = dy / 15.0f * 8.0f, u1 = dx / 15.0f * 8.0f;
    float t0 = copysignf(log2f(fabsf(u0) + 1.0f) * (1.0f/3.0f), u0);
    float t1 = copysignf(log2f(fabsf(u1) + 1.0f) * (1.0f/3.0f), u1);
    float acc[6] = {0,0,0,0,0,0};
    for (int u = t; u < 512; u += 128){
        float hv = fmaxf(w1[2*u]*t0 + w1[2*u+1]*t1 + b1[u], 0.0f);
        #pragma unroll
        for (int h = 0; h < 6; h++) acc[h] += hv * w2[h*512 + u];
    }
    __shared__ float red[6][128];
    #pragma unroll
    for (int h = 0; h < 6; h++) red[h][t] = acc[h];
    __syncthreads();
    for (int off = 64; off > 0; off >>= 1){
        if (t < off){
            #pragma unroll
            for (int h = 0; h < 6; h++) red[h][t] += red[h][t+off];
        }
        __syncthreads();
    }
    if (t < 6){
        float v = red[t][0];
        tbl[r*6 + t] = 16.0f / (1.0f + expf(-v));
    }
}

// ---------------- expand CPB bias to [h][256][256], log2 domain, -m_h -------
__global__ void k_bias(const float* __restrict__ tbl, const float* __restrict__ lsc,
                       float* __restrict__ bg)
{
    int r = blockIdx.x, h = blockIdx.y, c = threadIdx.x;
    int iy = r >> 4, ix = r & 15, my = c >> 4, mx = c & 15;
    int idx = (iy - my + 15)*31 + (ix - mx + 15);
    float scale = __expf(fminf(lsc[h], 4.6051702f));
    bg[((size_t)h*256 + r)*256 + c] = (tbl[idx*6 + h] - (scale + 16.0f)) * LOG2E;
}

// ---------------- tensor-core GEMM (bf16 hi/lo split, fp32 accum) ----------
// MODE 0: p1; 1: pw; 2: p2 (gate+res->BHWC, accumulates LN stats);
// MODE 3: qkv (inline LN from raw sums); 4: proj->NCHW
// B smem stride 264 -> conflict-free fragment loads. Epilogue stage (modes
// 2,3) is [pixel][68] -> conflict-free stores, vectorized reads.
template<int MODE>
__global__ void __launch_bounds__(256, 2)
k_gemm(const float* __restrict__ X, const float* __restrict__ W,
       const float* __restrict__ bias, const float* __restrict__ X2,
       const float* __restrict__ res, const float* __restrict__ qb,
       const float* __restrict__ vb, float* __restrict__ out,
       float* __restrict__ stats)
{
    // MODE 3 reinterprets: bias = ln_b, res = ln_g, X2 = raw stats (S, S2)
    extern __shared__ unsigned smem_u[];
    unsigned* Ah = smem_u;                  // 64*20
    unsigned* Al = Ah + 64*20;
    unsigned* Bh = Al + 64*20;              // 16*264
    unsigned* Bl = Bh + 16*264;
    float* sstat = (float*)(Bl + 16*264);   // mode 3: [256]*(mu,rs) @ 44032 B
    float* stg = (float*)smem_u;            // overlay (modes 2,3 epilogue): [256][68]

    const int t = threadIdx.x;
    const int wid = t >> 5, lane = t & 31;
    const int gid = lane >> 2, tig = lane & 3;
    const int m0w = (wid & 1) * 32;
    const int n0w = (wid >> 1) * 64;

    const int p0  = blockIdx.x * 256;
    const int co0 = blockIdx.y * 64;
    const int bz  = (MODE <= 2) ? blockIdx.z : 0;

    const float* Xb  = (MODE <= 2) ? (X + (size_t)bz*C*HW) : X;
    const float* X2b = (MODE == 2) ? (X2 + (size_t)bz*C*HW) : nullptr;

    float c[2][8][4];
    #pragma unroll
    for (int i = 0; i < 2; i++)
        #pragma unroll
        for (int j = 0; j < 8; j++)
            #pragma unroll
            for (int q = 0; q < 4; q++) c[i][j][q] = 0.0f;

    const int ar  = t >> 2;
    const int akq = (t & 3) * 8;

    // wait for predecessor before reading any produced buffer
    pdl_wait();

    if (MODE == 3){
        // per-pixel LN stats from raw sums
        float2 ssum = *(const float2*)&X2[(size_t)(p0 + t)*2];
        float mu = ssum.x * (1.0f/192.0f);
        float var = ssum.y * (1.0f/192.0f) - mu*mu;
        float rs = rsqrtf(var + 1e-5f);
        sstat[2*t] = mu; sstat[2*t+1] = rs;
    }

    for (int kc = 0; kc < 6; kc++){
        const int k0 = kc * 32;
        __syncthreads();
        {
            const float* wp = &W[(size_t)(co0 + ar)*192 + k0 + akq];
            float4 w0 = *(const float4*)wp;
            float4 w1 = *(const float4*)(wp + 4);
            uint4 h, l;
            split2(w0.x, w0.y, h.x, l.x);
            split2(w0.z, w0.w, h.y, l.y);
            split2(w1.x, w1.y, h.z, l.z);
            split2(w1.z, w1.w, h.w, l.w);
            *(uint4*)&Ah[ar*20 + akq/2] = h;
            *(uint4*)&Al[ar*20 + akq/2] = l;
        }
        if (MODE <= 2){
            const int bp  = (t & 63) * 4;
            const int bk2 = t >> 6;
            #pragma unroll
            for (int r = 0; r < 4; r++){
                int k2i = bk2 + r*4;
                int k = k0 + k2i*2;
                const float* xr = Xb + (size_t)k*HW + p0 + bp;
                float4 e = *(const float4*)xr;
                float4 o = *(const float4*)(xr + HW);
                if (MODE == 2){
                    const float* mr = X2b + (size_t)k*HW + p0 + bp;
                    float4 m1 = *(const float4*)mr;
                    float4 m2 = *(const float4*)(mr + HW);
                    e.x*=m1.x; e.y*=m1.y; e.z*=m1.z; e.w*=m1.w;
                    o.x*=m2.x; o.y*=m2.y; o.z*=m2.z; o.w*=m2.w;
                }
                uint4 h, l;
                split2(e.x, o.x, h.x, l.x);
                split2(e.y, o.y, h.y, l.y);
                split2(e.z, o.z, h.z, l.z);
                split2(e.w, o.w, h.w, l.w);
                *(uint4*)&Bh[k2i*264 + bp] = h;
                *(uint4*)&Bl[k2i*264 + bp] = l;
            }
        } else {
            const int fi = t & 7;
            const int k = k0 + fi*4;
            float4 gv, bv4;
            if (MODE == 3){
                gv  = *(const float4*)&res[k];     // ln gamma
                bv4 = *(const float4*)&bias[k];    // ln beta
            }
            #pragma unroll
            for (int r = 0; r < 8; r++){
                int pl = (t >> 3) + r*32;
                float4 v = *(const float4*)&Xb[(size_t)(p0 + pl)*192 + k];
                if (MODE == 3){
                    float2 st = *(const float2*)&sstat[2*pl];
                    v.x = (v.x - st.x)*st.y*gv.x + bv4.x;
                    v.y = (v.y - st.x)*st.y*gv.y + bv4.y;
                    v.z = (v.z - st.x)*st.y*gv.z + bv4.z;
                    v.w = (v.w - st.x)*st.y*gv.w + bv4.w;
                }
                unsigned h0, l0, h1, l1;
                split2(v.x, v.y, h0, l0);
                split2(v.z, v.w, h1, l1);
                Bh[(fi*2  )*264 + pl] = h0;
                Bh[(fi*2+1)*264 + pl] = h1;
                Bl[(fi*2  )*264 + pl] = l0;
                Bl[(fi*2+1)*264 + pl] = l1;
            }
        }
        __syncthreads();

        #pragma unroll
        for (int ks = 0; ks < 2; ks++){
            const int kb = ks * 8;
            unsigned ah[2][4], al2[2][4];
            #pragma unroll
            for (int mt = 0; mt < 2; mt++){
                int mr = m0w + mt*16 + gid;
                ah[mt][0]  = Ah[mr*20 + kb + tig];
                ah[mt][1]  = Ah[(mr+8)*20 + kb + tig];
                ah[mt][2]  = Ah[mr*20 + kb + tig + 4];
                ah[mt][3]  = Ah[(mr+8)*20 + kb + tig + 4];
                al2[mt][0] = Al[mr*20 + kb + tig];
                al2[mt][1] = Al[(mr+8)*20 + kb + tig];
                al2[mt][2] = Al[mr*20 + kb + tig + 4];
                al2[mt][3] = Al[(mr+8)*20 + kb + tig + 4];
            }
            #pragma unroll
            for (int nt = 0; nt < 8; nt++){
                int nn = n0w + nt*8 + gid;
                unsigned bh0 = Bh[(kb+tig  )*264 + nn];
                unsigned bh1 = Bh[(kb+tig+4)*264 + nn];
                unsigned bl0 = Bl[(kb+tig  )*264 + nn];
                unsigned bl1 = Bl[(kb+tig+4)*264 + nn];
                #pragma unroll
                for (int mt = 0; mt < 2; mt++){
                    mma_bf16(c[mt][nt], ah[mt],  bh0, bh1);
                    mma_bf16(c[mt][nt], ah[mt],  bl0, bl1);
                    mma_bf16(c[mt][nt], al2[mt], bh0, bh1);
                }
            }
        }
    }

    if (MODE == 0 || MODE == 1){
        #pragma unroll
        for (int mt = 0; mt < 2; mt++){
            #pragma unroll
            for (int s = 0; s < 2; s++){
                int rl = m0w + mt*16 + gid + s*8;
                float bv = bias[co0 + rl];
                float* orow = out + ((size_t)bz*C + co0 + rl)*HW + p0;
                #pragma unroll
                for (int nt = 0; nt < 8; nt++){
                    int cs = n0w + nt*8 + tig*2;
                    float v0 = c[mt][nt][s*2+0] + bv;
                    float v1 = c[mt][nt][s*2+1] + bv;
                    if (MODE == 0){
                        v0 = 0.5f*v0*(1.0f + erff(v0*0.70710678f));
                        v1 = 0.5f*v1*(1.0f + erff(v1*0.70710678f));
                    }
                    float2 v = {v0, v1};
                    *(float2*)&orow[cs] = v;
                }
            }
        }
    } else if (MODE == 4){
        const int bb = p0 >> 14;
        const int hw0 = p0 & 16383;
        #pragma unroll
        for (int mt = 0; mt < 2; mt++){
            #pragma unroll
            for (int s = 0; s < 2; s++){
                int rl = m0w + mt*16 + gid + s*8;
                float bv = bias[co0 + rl];
                float* orow = out + ((size_t)bb*C + co0 + rl)*HW + hw0;
                #pragma unroll
                for (int nt = 0; nt < 8; nt++){
                    int cs = n0w + nt*8 + tig*2;
                    float2 v = {c[mt][nt][s*2+0] + bv, c[mt][nt][s*2+1] + bv};
                    *(float2*)&orow[cs] = v;
                }
            }
        }
    } else {
        // modes 2,3: stage transposed [pixel][68] -> conflict-free STS,
        // vectorized LDS.128 reads
        __syncthreads();
        #pragma unroll
        for (int mt = 0; mt < 2; mt++){
            #pragma unroll
            for (int s = 0; s < 2; s++){
                int rl = m0w + mt*16 + gid + s*8;
                float bv;
                if (MODE == 3){
                    int co = co0 + rl;
                    bv = (co < 192) ? qb[co] : (co < 384 ? 0.0f : vb[co - 384]);
                } else {
                    bv = bias[co0 + rl];
                }
                const float* rrow = (MODE == 2)
                    ? (res + ((size_t)bz*C + co0 + rl)*HW + p0) : nullptr;
                #pragma unroll
                for (int nt = 0; nt < 8; nt++){
                    int cs = n0w + nt*8 + tig*2;
                    float v0 = c[mt][nt][s*2+0] + bv;
                    float v1 = c[mt][nt][s*2+1] + bv;
                    if (MODE == 2){
                        float2 rv = *(const float2*)&rrow[cs];
                        v0 += rv.x; v1 += rv.y;
                    }
                    stg[(size_t)cs*68 + rl]       = v0;
                    stg[(size_t)(cs+1)*68 + rl]   = v1;
                }
            }
        }
        __syncthreads();
        const int ldo = (MODE == 3) ? 576 : 192;
        const size_t pbase = (MODE == 3) ? (size_t)p0 : ((size_t)bz*HW + p0);
        #pragma unroll
        for (int r = 0; r < 4; r++){
            int pl = (t >> 2) + r*64;
            int cq = (t & 3) * 16;
            float vals[16];
            const float* rowp = &stg[(size_t)pl*68 + cq];
            *(float4*)&vals[0]  = *(const float4*)&rowp[0];
            *(float4*)&vals[4]  = *(const float4*)&rowp[4];
            *(float4*)&vals[8]  = *(const float4*)&rowp[8];
            *(float4*)&vals[12] = *(const float4*)&rowp[12];
            if (MODE == 2){
                float s = 0.0f, s2 = 0.0f;
                #pragma unroll
                for (int j = 0; j < 16; j++){ s += vals[j]; s2 += vals[j]*vals[j]; }
                s  += __shfl_xor_sync(0xffffffffu, s, 1);
                s  += __shfl_xor_sync(0xffffffffu, s, 2);
                s2 += __shfl_xor_sync(0xffffffffu, s2, 1);
                s2 += __shfl_xor_sync(0xffffffffu, s2, 2);
                if ((t & 3) == 0){
                    size_t px = (size_t)bz*HW + p0 + pl;
                    atomicAdd(&stats[px*2],     s);
                    atomicAdd(&stats[px*2 + 1], s2);
                }
            }
            float* op = out + (pbase + pl)*ldo + co0 + cq;
            *(float4*)&op[0]  = *(float4*)&vals[0];
            *(float4*)&op[4]  = *(float4*)&vals[4];
            *(float4*)&op[8]  = *(float4*)&vals[8];
            *(float4*)&op[12] = *(float4*)&vals[12];
        }
    }
}

// ---------------- fused depthwise 5x5 + 5x5 dil3 (64x64 tile, 2-row conv1) --
// dynamic smem: wts[52] | s0[80][84] | s1[76][84]
__global__ void __launch_bounds__(256)
k_dwf(const float* __restrict__ in, const float* __restrict__ w1,
      const float* __restrict__ b1, const float* __restrict__ w2,
      const float* __restrict__ b2, float* __restrict__ out)
{
    extern __shared__ float dsm[];
    float* wts = dsm;                 // 52
    float* s0  = dsm + 52;            // 80*84
    float* s1  = s0 + 80*84;          // 76*84

    const int plane = blockIdx.y;     // b*C + c
    const int c = plane % C;
    const int tile = blockIdx.x;      // 0..3
    const int y0 = (tile >> 1) * 64, x0 = (tile & 1) * 64;
    const int t = threadIdx.x;

    // independent prologue: stage weights (harness inputs) before waiting
    if (t < 25) wts[t] = w1[c*25 + t];
    else if (t < 50) wts[t] = w2[c*25 + t - 25];
    else if (t == 50) wts[50] = b1[c];
    else if (t == 51) wts[51] = b2[c];

    pdl_wait();

    const float* ip = in + ((size_t)plane << 14);
    for (int idx = t; idx < 80*84; idx += 256){
        int yy = idx / 84, xx = idx - yy*84;
        int gy = y0 - 8 + yy, gx = x0 - 8 + xx;
        s0[yy*84 + xx] = ((unsigned)gy < 128u && (unsigned)gx < 128u) ? ip[gy*128+gx] : 0.0f;
    }
    __syncthreads();

    // conv1 (dense 5x5): 380 units, each 2 rows x 8 cols from 6 input rows
    for (int u = t; u < 380; u += 256){
        int rp = u / 10, cg = u - 10*rp;
        int r = rp * 2;                  // s1 rows r, r+1 (r <= 74)
        int c0 = cg * 8;                 // s1 cols c0..c0+7
        float a0[8], a1[8];
        #pragma unroll
        for (int cc = 0; cc < 8; cc++){ a0[cc] = wts[50]; a1[cc] = wts[50]; }
        #pragma unroll
        for (int i2 = 0; i2 < 6; i2++){
            float row[12];
            const float* sp = &s0[(r+i2)*84 + c0];
            *(float4*)&row[0] = *(const float4*)&sp[0];
            *(float4*)&row[4] = *(const float4*)&sp[4];
            *(float4*)&row[8] = *(const float4*)&sp[8];
            if (i2 < 5){
                #pragma unroll
                for (int j = 0; j < 5; j++){
                    float wv = wts[i2*5+j];
                    #pragma unroll
                    for (int cc = 0; cc < 8; cc++)
                        a0[cc] = fmaf(wv, row[cc+j], a0[cc]);
                }
            }
            if (i2 > 0){
                #pragma unroll
                for (int j = 0; j < 5; j++){
                    float wv = wts[(i2-1)*5+j];
                    #pragma unroll
                    for (int cc = 0; cc < 8; cc++)
                        a1[cc] = fmaf(wv, row[cc+j], a1[cc]);
                }
            }
        }
        int gy0 = y0 - 6 + r;
        bool ok0 = (unsigned)gy0 < 128u;
        bool ok1 = (unsigned)(gy0+1) < 128u;
        #pragma unroll
        for (int cc = 0; cc < 8; cc++){
            int gx = x0 - 6 + c0 + cc;
            bool cok = (unsigned)gx < 128u;
            s1[r*84 + c0 + cc]     = (ok0 && cok) ? a0[cc] : 0.0f;
            s1[(r+1)*84 + c0 + cc] = (ok1 && cok) ? a1[cc] : 0.0f;
        }
    }
    __syncthreads();

    // conv2 (5x5 dil 3): 1024 units, each 1 row x 4 cols
    for (int u = t; u < 1024; u += 256){
        int row = u >> 4, cg = u & 15;
        int c0 = cg * 4;
        float acc[4];
        #pragma unroll
        for (int cc = 0; cc < 4; cc++) acc[cc] = wts[51];
        #pragma unroll
        for (int i = 0; i < 5; i++){
            float rw[16];
            const float* sp = &s1[(row+3*i)*84 + c0];
            *(float4*)&rw[0]  = *(const float4*)&sp[0];
            *(float4*)&rw[4]  = *(const float4*)&sp[4];
            *(float4*)&rw[8]  = *(const float4*)&sp[8];
            *(float4*)&rw[12] = *(const float4*)&sp[12];
            #pragma unroll
            for (int j = 0; j < 5; j++){
                float wv = wts[25+i*5+j];
                #pragma unroll
                for (int cc = 0; cc < 4; cc++)
                    acc[cc] = fmaf(wv, rw[3*j+cc], acc[cc]);
            }
        }
        *(float4*)&out[((size_t)plane << 14) + (y0+row)*128 + x0 + c0] = *(float4*)&acc[0];
    }
}

// ---------------- SwinV2 cosine window attention (tensor-core flash) --------
// fixed-shift softmax in log2 domain; 32-col half-chunks, 2 CTAs/SM
__global__ void __launch_bounds__(256, 2)
k_attn(const float* __restrict__ qkv, const float* __restrict__ bgl,
       const float* __restrict__ lsc, float* __restrict__ out)
{
    extern __shared__ unsigned sm[];
    unsigned* Kh = sm;                     // [16][264]
    unsigned* Kl = Kh + 16*264;
    unsigned* Vh = Kl + 16*264;            // [128][40]
    unsigned* Vl = Vh + 128*40;
    float* qs = (float*)(Vl + 128*40);     // [256]

    const int w = blockIdx.x, h = blockIdx.y, t = threadIdx.x;
    const int b = w >> 6, wy = (w >> 3) & 7, wx = w & 7;
    const int wid = t >> 5, lane = t & 31, gid = lane >> 2, tig = lane & 3;
    const float scale = __expf(fminf(lsc[h], 4.6051702f));
    const size_t pixbase = (size_t)b*HW + (size_t)(wy*16)*128 + wx*16;

    pdl_wait();

    {
        const int tok = t;
        const size_t pp = pixbase + (size_t)(tok >> 4)*128 + (tok & 15);
        const float* qr = qkv + pp*576 + h*32;
        const float* kr = qr + 192;
        float kv[32]; float ssq = 0.0f, ssk = 0.0f;
        #pragma unroll
        for (int d = 0; d < 8; d++){
            float4 q4 = ((const float4*)qr)[d];
            ssq += q4.x*q4.x + q4.y*q4.y + q4.z*q4.z + q4.w*q4.w;
            float4 k4 = ((const float4*)kr)[d];
            kv[4*d]=k4.x; kv[4*d+1]=k4.y; kv[4*d+2]=k4.z; kv[4*d+3]=k4.w;
            ssk += k4.x*k4.x + k4.y*k4.y + k4.z*k4.z + k4.w*k4.w;
        }
        qs[tok] = scale * LOG2E / fmaxf(sqrtf(ssq), 1e-12f);
        float ki = 1.0f / fmaxf(sqrtf(ssk), 1e-12f);
        #pragma unroll
        for (int d2 = 0; d2 < 16; d2++){
            unsigned hh, ll;
            split2(kv[2*d2]*ki, kv[2*d2+1]*ki, hh, ll);
            Kh[d2*264 + tok] = hh;
            Kl[d2*264 + tok] = ll;
        }
    }
    {
        const int t2 = t >> 1, dh = (t & 1) * 16;
        const size_t pa = pixbase + (size_t)((2*t2) >> 4)*128 + ((2*t2) & 15);
        const size_t pb = pixbase + (size_t)((2*t2+1) >> 4)*128 + ((2*t2+1) & 15);
        const float* v0 = qkv + pa*576 + 384 + h*32 + dh;
        const float* v1 = qkv + pb*576 + 384 + h*32 + dh;
        #pragma unroll
        for (int dq = 0; dq < 4; dq++){
            float4 a = ((const float4*)v0)[dq];
            float4 bb = ((const float4*)v1)[dq];
            unsigned hh, ll;
            split2(a.x, bb.x, hh, ll); Vh[t2*40+dh+4*dq+0]=hh; Vl[t2*40+dh+4*dq+0]=ll;
            split2(a.y, bb.y, hh, ll); Vh[t2*40+dh+4*dq+1]=hh; Vl[t2*40+dh+4*dq+1]=ll;
            split2(a.z, bb.z, hh, ll); Vh[t2*40+dh+4*dq+2]=hh; Vl[t2*40+dh+4*dq+2]=ll;
            split2(a.w, bb.w, hh, ll); Vh[t2*40+dh+4*dq+3]=hh; Vl[t2*40+dh+4*dq+3]=ll;
        }
    }
    __syncthreads();

    unsigned qh[2][2][4], ql[2][2][4];
    #pragma unroll
    for (int mt = 0; mt < 2; mt++){
        int r1 = wid*32 + mt*16 + gid, r2 = r1 + 8;
        float s1 = qs[r1], s2 = qs[r2];
        const float* q1 = qkv + (pixbase + (size_t)(r1>>4)*128 + (r1&15))*576 + h*32;
        const float* q2 = qkv + (pixbase + (size_t)(r2>>4)*128 + (r2&15))*576 + h*32;
        #pragma unroll
        for (int ks = 0; ks < 2; ks++){
            float2 e1 = *(const float2*)(q1 + 16*ks + 2*tig);
            float2 e2 = *(const float2*)(q2 + 16*ks + 2*tig);
            float2 f1 = *(const float2*)(q1 + 16*ks + 8 + 2*tig);
            float2 f2 = *(const float2*)(q2 + 16*ks + 8 + 2*tig);
            split2(e1.x*s1, e1.y*s1, qh[mt][ks][0], ql[mt][ks][0]);
            split2(e2.x*s2, e2.y*s2, qh[mt][ks][1], ql[mt][ks][1]);
            split2(f1.x*s1, f1.y*s1, qh[mt][ks][2], ql[mt][ks][2]);
            split2(f2.x*s2, f2.y*s2, qh[mt][ks][3], ql[mt][ks][3]);
        }
    }

    float l[4] = {0,0,0,0};
    float o[2][4][4];
    #pragma unroll
    for (int i=0;i<2;i++) for (int j=0;j<4;j++) for (int q=0;q<4;q++) o[i][j][q]=0.0f;

    const float* bg = bgl + (size_t)h*256*256;

    for (int ch = 0; ch < 8; ch++){
        const int c0 = ch * 32;
        float c[2][4][4];
        #pragma unroll
        for (int i=0;i<2;i++) for (int j=0;j<4;j++) for (int q=0;q<4;q++) c[i][j][q]=0.0f;

        #pragma unroll
        for (int ks = 0; ks < 2; ks++){
            #pragma unroll
            for (int nt = 0; nt < 4; nt++){
                int n = c0 + nt*8 + gid;
                unsigned bh0 = Kh[(8*ks+tig  )*264 + n];
                unsigned bh1 = Kh[(8*ks+tig+4)*264 + n];
                unsigned bl0 = Kl[(8*ks+tig  )*264 + n];
                unsigned bl1 = Kl[(8*ks+tig+4)*264 + n];
                #pragma unroll
                for (int mt = 0; mt < 2; mt++){
                    mma_bf16(c[mt][nt], qh[mt][ks], bh0, bh1);
                    mma_bf16(c[mt][nt], qh[mt][ks], bl0, bl1);
                    mma_bf16(c[mt][nt], ql[mt][ks], bh0, bh1);
                }
            }
        }

        #pragma unroll
        for (int tt = 0; tt < 2; tt++){
            unsigned ph[2][4], pl[2][4];
            #pragma unroll
            for (int mt = 0; mt < 2; mt++){
                int r1 = wid*32 + mt*16 + gid, r2 = r1 + 8;
                int cc0 = c0 + (2*tt)*8 + 2*tig;
                int cc1 = c0 + (2*tt+1)*8 + 2*tig;
                float2 ba = *(const float2*)&bg[(size_t)r1*256 + cc0];
                float2 bb2 = *(const float2*)&bg[(size_t)r2*256 + cc0];
                float2 bc = *(const float2*)&bg[(size_t)r1*256 + cc1];
                float2 bd = *(const float2*)&bg[(size_t)r2*256 + cc1];
                float p0 = fexp2(c[mt][2*tt  ][0] + ba.x);
                float p1 = fexp2(c[mt][2*tt  ][1] + ba.y);
                float p2 = fexp2(c[mt][2*tt  ][2] + bb2.x);
                float p3 = fexp2(c[mt][2*tt  ][3] + bb2.y);
                float p4 = fexp2(c[mt][2*tt+1][0] + bc.x);
                float p5 = fexp2(c[mt][2*tt+1][1] + bc.y);
                float p6 = fexp2(c[mt][2*tt+1][2] + bd.x);
                float p7 = fexp2(c[mt][2*tt+1][3] + bd.y);
                l[2*mt]   += p0 + p1 + p4 + p5;
                l[2*mt+1] += p2 + p3 + p6 + p7;
                split2(p0, p1, ph[mt][0], pl[mt][0]);
                split2(p2, p3, ph[mt][1], pl[mt][1]);
                split2(p4, p5, ph[mt][2], pl[mt][2]);
                split2(p6, p7, ph[mt][3], pl[mt][3]);
            }
            const int base = (c0 + 16*tt) >> 1;
            #pragma unroll
            for (int nt2 = 0; nt2 < 4; nt2++){
                int dcol = nt2*8 + gid;
                unsigned vh0 = Vh[(base+tig  )*40 + dcol];
                unsigned vh1 = Vh[(base+tig+4)*40 + dcol];
                unsigned vl0 = Vl[(base+tig  )*40 + dcol];
                unsigned vl1 = Vl[(base+tig+4)*40 + dcol];
                #pragma unroll
                for (int mt = 0; mt < 2; mt++){
                    mma_bf16(o[mt][nt2], ph[mt], vh0, vh1);
                    mma_bf16(o[mt][nt2], ph[mt], vl0, vl1);
                    mma_bf16(o[mt][nt2], pl[mt], vh0, vh1);
                }
            }
        }
    }

    #pragma unroll
    for (int q = 0; q < 4; q++){
        l[q] += __shfl_xor_sync(0xffffffffu, l[q], 1);
        l[q] += __shfl_xor_sync(0xffffffffu, l[q], 2);
        l[q] = 1.0f / l[q];
    }
    #pragma unroll
    for (int mt = 0; mt < 2; mt++){
        int r1 = wid*32 + mt*16 + gid, r2 = r1 + 8;
        float* o1 = out + (pixbase + (size_t)(r1>>4)*128 + (r1&15))*192 + h*32;
        float* o2 = out + (pixbase + (size_t)(r2>>4)*128 + (r2&15))*192 + h*32;
        #pragma unroll
        for (int nt2 = 0; nt2 < 4; nt2++){
            int dc = nt2*8 + 2*tig;
            float2 v1 = { o[mt][nt2][0]*l[2*mt],   o[mt][nt2][1]*l[2*mt] };
            float2 v2 = { o[mt][nt2][2]*l[2*mt+1], o[mt][nt2][3]*l[2*mt+1] };
            *(float2*)(o1 + dc) = v1;
            *(float2*)(o2 + dc) = v2;
        }
    }
}

// ---------------- PDL launch helper -----------------------------------------
static void pdl_launch(const void* fn, dim3 grid, int smem, void** args)
{
    cudaLaunchConfig_t cfg = {};
    cfg.gridDim = grid;
    cfg.blockDim = dim3(256, 1, 1);
    cfg.dynamicSmemBytes = (size_t)smem;
    cfg.stream = 0;
    cudaLaunchAttribute attr[1];
    attr[0].id = cudaLaunchAttributeProgrammaticStreamSerialization;
    attr[0].val.programmaticStreamSerializationAllowed = 1;
    cfg.attrs = attr;
    cfg.numAttrs = 1;
    cudaLaunchKernelExC(&cfg, fn, args);
}

// ---------------------------------------------------------------------------
extern "C" void kernel_launch(void* const* d_in, const int* in_sizes, int n_in,
                              void* d_out, int out_size)
{
    const float* x      = (const float*)d_in[0];
    const float* p1_w   = (const float*)d_in[1];
    const float* p1_b   = (const float*)d_in[2];
    const float* pw_w   = (const float*)d_in[3];
    const float* pw_b   = (const float*)d_in[4];
    const float* dw_w   = (const float*)d_in[5];
    const float* dw_b   = (const float*)d_in[6];
    const float* dd_w   = (const float*)d_in[7];
    const float* dd_b   = (const float*)d_in[8];
    const float* p2_w   = (const float*)d_in[9];
    const float* p2_b   = (const float*)d_in[10];
    const float* ln_g   = (const float*)d_in[11];
    const float* ln_b   = (const float*)d_in[12];
    const float* qkv_w  = (const float*)d_in[13];
    const float* q_bias = (const float*)d_in[14];
    const float* v_bias = (const float*)d_in[15];
    const float* lsc    = (const float*)d_in[16];
    const float* cpb_w1 = (const float*)d_in[17];
    const float* cpb_b1 = (const float*)d_in[18];
    const float* cpb_w2 = (const float*)d_in[19];
    const float* proj_w = (const float*)d_in[20];
    const float* proj_b = (const float*)d_in[21];
    float* outp = (float*)d_out;

    float *gy, *ga, *gb, *gq, *gt, *gbias, *gst;
    cudaGetSymbolAddress((void**)&gy, g_y);
    cudaGetSymbolAddress((void**)&ga, g_a);
    cudaGetSymbolAddress((void**)&gb, g_b);
    cudaGetSymbolAddress((void**)&gq, g_qkv);
    cudaGetSymbolAddress((void**)&gt, g_tbl);
    cudaGetSymbolAddress((void**)&gbias, g_bias);
    cudaGetSymbolAddress((void**)&gst, g_stats);

    const int ATTN_SMEM = (2*16*264 + 2*128*40 + 256) * 4;
    cudaFuncSetAttribute(k_attn, cudaFuncAttributeMaxDynamicSharedMemorySize, ATTN_SMEM);
    const int GEMM_SMEM_LOAD  = (64*20*2 + 16*264*2) * 4;        // 44032
    const int GEMM_SMEM_STAGE = 256*68*4;                        // 69632 ([pixel][68] overlay)
    cudaFuncSetAttribute(k_gemm<2>, cudaFuncAttributeMaxDynamicSharedMemorySize, GEMM_SMEM_STAGE);
    cudaFuncSetAttribute(k_gemm<3>, cudaFuncAttributeMaxDynamicSharedMemorySize, GEMM_SMEM_STAGE);
    const int DWF_SMEM = (52 + 80*84 + 76*84) * 4;               // 52624
    cudaFuncSetAttribute(k_dwf, cudaFuncAttributeMaxDynamicSharedMemorySize, DWF_SMEM);

    dim3 gNCHW(HW/256, 3, BATCH);

    // zero LN partial sums (accumulated atomically by p2 epilogue)
    cudaMemsetAsync(gst, 0, (size_t)NPIX*2*sizeof(float));

    // CPB bias table + expansion (normal launches)
    k_cpb<<<961, 128>>>(cpb_w1, cpb_b1, cpb_w2, gt);
    k_bias<<<dim3(256, NH), 256>>>(gt, lsc, gbias);

    // main chain: PDL launches (tail-fill across kernel boundaries)
    {
        void* a0[] = {(void*)&x, (void*)&p1_w, (void*)&p1_b, (void*)&x, (void*)&x,
                      (void*)&x, (void*)&x, (void*)&gy, (void*)&gst};
        pdl_launch((const void*)k_gemm<0>, gNCHW, GEMM_SMEM_LOAD, a0);

        void* a1[] = {(void*)&gy, (void*)&pw_w, (void*)&pw_b, (void*)&x, (void*)&x,
                      (void*)&x, (void*)&x, (void*)&ga, (void*)&gst};
        pdl_launch((const void*)k_gemm<1>, gNCHW, GEMM_SMEM_LOAD, a1);

        void* a2[] = {(void*)&ga, (void*)&dw_w, (void*)&dw_b, (void*)&dd_w,
                      (void*)&dd_b, (void*)&gb};
        pdl_launch((const void*)k_dwf, dim3(4, BATCH*C), DWF_SMEM, a2);

        void* a3[] = {(void*)&gy, (void*)&p2_w, (void*)&p2_b, (void*)&gb, (void*)&x,
                      (void*)&x, (void*)&x, (void*)&ga, (void*)&gst};
        pdl_launch((const void*)k_gemm<2>, gNCHW, GEMM_SMEM_STAGE, a3);

        void* a4[] = {(void*)&ga, (void*)&qkv_w, (void*)&ln_b, (void*)&gst, (void*)&ln_g,
                      (void*)&q_bias, (void*)&v_bias, (void*)&gq, (void*)&gst};
        pdl_launch((const void*)k_gemm<3>, dim3(NPIX/256, 9), GEMM_SMEM_STAGE, a4);

        void* a5[] = {(void*)&gq, (void*)&gbias, (void*)&lsc, (void*)&gy};
        pdl_launch((const void*)k_attn, dim3(NWIN, NH), ATTN_SMEM, a5);

        void* a6[] = {(void*)&gy, (void*)&proj_w, (void*)&proj_b, (void*)&x, (void*)&x,
                      (void*)&x, (void*)&x, (void*)&outp, (void*)&gst};
        pdl_launch((const void*)k_gemm<4>, dim3(NPIX/256, 3), GEMM_SMEM_LOAD, a6);
    }
}